// round 1
// baseline (speedup 1.0000x reference)
#include <cuda_runtime.h>
#include <cuda_bf16.h>
#include <math.h>

#define DIM 2048
#define NH 16
#define HD 128
#define BSZ 2
#define SEQLEN 2048
#define MROWS (BSZ * SEQLEN)

// Scratch (static device arrays — allocation-free per harness rules)
__device__ float g_q[(size_t)MROWS * DIM];
__device__ float g_k[(size_t)MROWS * DIM];
__device__ float g_v[(size_t)MROWS * DIM];
__device__ float g_att[(size_t)MROWS * DIM];

// ---------------------------------------------------------------------------
// GEMM: C[M][N] = sum_k A[m][k] * B[n][k]   (A row-major MxK, B row-major NxK)
// 128x128 tile, BK=8, 256 threads, 8x8 per-thread register tile.
// ---------------------------------------------------------------------------
__global__ __launch_bounds__(256) void gemm_nt_kernel(
    const float* __restrict__ A, const float* __restrict__ B,
    float* __restrict__ C, int M, int N, int K)
{
    __shared__ float As[8][132];
    __shared__ float Bs[8][132];

    const int bm = blockIdx.y * 128;
    const int bn = blockIdx.x * 128;
    const int tid = threadIdx.x;
    const int tr = tid >> 4;          // 0..15
    const int tc = tid & 15;          // 0..15
    const int lr = tid >> 1;          // 0..127
    const int lk = (tid & 1) << 2;    // 0 or 4

    const float* Ag = A + (size_t)(bm + lr) * K + lk;
    const float* Bg = B + (size_t)(bn + lr) * K + lk;

    float acc[8][8];
#pragma unroll
    for (int i = 0; i < 8; ++i)
#pragma unroll
        for (int j = 0; j < 8; ++j) acc[i][j] = 0.0f;

    for (int k0 = 0; k0 < K; k0 += 8) {
        float4 av = *(const float4*)(Ag + k0);
        float4 bv = *(const float4*)(Bg + k0);
        __syncthreads();
        As[lk + 0][lr] = av.x;
        As[lk + 1][lr] = av.y;
        As[lk + 2][lr] = av.z;
        As[lk + 3][lr] = av.w;
        Bs[lk + 0][lr] = bv.x;
        Bs[lk + 1][lr] = bv.y;
        Bs[lk + 2][lr] = bv.z;
        Bs[lk + 3][lr] = bv.w;
        __syncthreads();
#pragma unroll
        for (int kk = 0; kk < 8; ++kk) {
            float4 a0 = *(const float4*)&As[kk][tr * 8];
            float4 a1 = *(const float4*)&As[kk][tr * 8 + 4];
            float4 b0 = *(const float4*)&Bs[kk][tc * 8];
            float4 b1 = *(const float4*)&Bs[kk][tc * 8 + 4];
            float ra[8] = {a0.x, a0.y, a0.z, a0.w, a1.x, a1.y, a1.z, a1.w};
            float rb[8] = {b0.x, b0.y, b0.z, b0.w, b1.x, b1.y, b1.z, b1.w};
#pragma unroll
            for (int i = 0; i < 8; ++i)
#pragma unroll
                for (int j = 0; j < 8; ++j)
                    acc[i][j] = fmaf(ra[i], rb[j], acc[i][j]);
        }
    }

#pragma unroll
    for (int i = 0; i < 8; ++i) {
        float* Cp = C + (size_t)(bm + tr * 8 + i) * N + bn + tc * 8;
        float4 c0 = make_float4(acc[i][0], acc[i][1], acc[i][2], acc[i][3]);
        float4 c1 = make_float4(acc[i][4], acc[i][5], acc[i][6], acc[i][7]);
        *(float4*)Cp = c0;
        *(float4*)(Cp + 4) = c1;
    }
}

// ---------------------------------------------------------------------------
// RoPE (interleaved pairs), applied in-place to Q and K. start_pos = 0.
// Layout: [b][s][h*HD + 2p(+1)], cos/sin: [s][p], p in [0,64)
// ---------------------------------------------------------------------------
__global__ __launch_bounds__(256) void rope_kernel(
    float* __restrict__ q, float* __restrict__ k,
    const float* __restrict__ cosf, const float* __restrict__ sinf)
{
    int i = blockIdx.x * blockDim.x + threadIdx.x;   // pair index
    const int total = BSZ * SEQLEN * NH * (HD / 2);  // 4,194,304
    if (i >= total) return;
    int p = i & 63;
    int hh = (i >> 6) & 15;
    int s = (i >> 10) & 2047;
    int bb = i >> 21;
    size_t addr = ((size_t)(bb * SEQLEN + s)) * DIM + hh * HD + 2 * p;
    float c = cosf[s * 64 + p];
    float sn = sinf[s * 64 + p];
    float a = q[addr], b2 = q[addr + 1];
    q[addr]     = a * c - b2 * sn;
    q[addr + 1] = a * sn + b2 * c;
    a = k[addr]; b2 = k[addr + 1];
    k[addr]     = a * c - b2 * sn;
    k[addr + 1] = a * sn + b2 * c;
}

// ---------------------------------------------------------------------------
// Flash attention (fp32, causal). BQ = BKV = 64, 256 threads.
// Q/K stored transposed in smem ([d][m], stride 65) for conflict-free dots.
// ---------------------------------------------------------------------------
#define BQ 64
#define BKV 64
#define QS_STRIDE 65
#define SS_STRIDE 65
#define FLASH_SMEM_FLOATS (2 * HD * QS_STRIDE + BKV * HD + BQ * SS_STRIDE + 3 * BQ)
#define FLASH_SMEM_BYTES (FLASH_SMEM_FLOATS * 4)

__global__ __launch_bounds__(256) void flash_kernel(
    const float* __restrict__ Q, const float* __restrict__ K,
    const float* __restrict__ V, float* __restrict__ O)
{
    extern __shared__ float sm[];
    float* Qs = sm;                      // [HD][65]  (transposed: [d][m])
    float* Ks = Qs + HD * QS_STRIDE;     // [HD][65]  (transposed: [d][n])
    float* Vs = Ks + HD * QS_STRIDE;     // [BKV][HD] (row-major)
    float* Ss = Vs + BKV * HD;           // [BQ][65]
    float* m_s = Ss + BQ * SS_STRIDE;
    float* l_s = m_s + BQ;
    float* sc_s = l_s + BQ;

    const int qt = (int)gridDim.x - 1 - (int)blockIdx.x;  // heavy tiles first
    const int bh = blockIdx.y;
    const int b = bh >> 4;
    const int h = bh & 15;
    const int tid = threadIdx.x;
    const int ty = tid >> 4;   // 0..15
    const int tx = tid & 15;   // 0..15

    const size_t head_base = (size_t)b * SEQLEN * DIM + (size_t)h * HD;
    const float* Qg = Q + head_base + (size_t)(qt * BQ) * DIM;

    // Load Q tile transposed
#pragma unroll
    for (int it = 0; it < 8; ++it) {
        int idx = tid + it * 256;          // 0..2047
        int m = idx >> 5;                  // row (0..63)
        int d4 = (idx & 31) << 2;          // 0..124
        float4 v4 = *(const float4*)(Qg + (size_t)m * DIM + d4);
        Qs[(d4 + 0) * QS_STRIDE + m] = v4.x;
        Qs[(d4 + 1) * QS_STRIDE + m] = v4.y;
        Qs[(d4 + 2) * QS_STRIDE + m] = v4.z;
        Qs[(d4 + 3) * QS_STRIDE + m] = v4.w;
    }
    if (tid < BQ) { m_s[tid] = -1e30f; l_s[tid] = 0.0f; }

    float o[4][8];
#pragma unroll
    for (int i = 0; i < 4; ++i)
#pragma unroll
        for (int j = 0; j < 8; ++j) o[i][j] = 0.0f;

    __syncthreads();

    const float scale = 0.08838834764831845f;  // 1/sqrt(128)
    const int ntiles = qt + 1;
    for (int kt = 0; kt < ntiles; ++kt) {
        const float* Kg = K + head_base + (size_t)(kt * BKV) * DIM;
        const float* Vg = V + head_base + (size_t)(kt * BKV) * DIM;
#pragma unroll
        for (int it = 0; it < 8; ++it) {
            int idx = tid + it * 256;
            int m = idx >> 5;
            int d4 = (idx & 31) << 2;
            float4 kv4 = *(const float4*)(Kg + (size_t)m * DIM + d4);
            Ks[(d4 + 0) * QS_STRIDE + m] = kv4.x;
            Ks[(d4 + 1) * QS_STRIDE + m] = kv4.y;
            Ks[(d4 + 2) * QS_STRIDE + m] = kv4.z;
            Ks[(d4 + 3) * QS_STRIDE + m] = kv4.w;
            float4 vv4 = *(const float4*)(Vg + (size_t)m * DIM + d4);
            *(float4*)&Vs[m * HD + d4] = vv4;
        }
        __syncthreads();

        // Scores: s[i][j] = Q[ty*4+i] . K[tx*4+j]
        float s[4][4];
#pragma unroll
        for (int i = 0; i < 4; ++i)
#pragma unroll
            for (int j = 0; j < 4; ++j) s[i][j] = 0.0f;

#pragma unroll 4
        for (int d = 0; d < HD; ++d) {
            float ra[4], rb[4];
#pragma unroll
            for (int i = 0; i < 4; ++i) ra[i] = Qs[d * QS_STRIDE + ty * 4 + i];
#pragma unroll
            for (int j = 0; j < 4; ++j) rb[j] = Ks[d * QS_STRIDE + tx * 4 + j];
#pragma unroll
            for (int i = 0; i < 4; ++i)
#pragma unroll
                for (int j = 0; j < 4; ++j)
                    s[i][j] = fmaf(ra[i], rb[j], s[i][j]);
        }

        // Scale + causal mask (only diagonal tile) + write to smem
        const bool diag = (kt == qt);
#pragma unroll
        for (int i = 0; i < 4; ++i) {
            int rr = ty * 4 + i;
#pragma unroll
            for (int j = 0; j < 4; ++j) {
                int cc = tx * 4 + j;
                float val = s[i][j] * scale;
                if (diag && cc > rr) val = -1e30f;
                Ss[rr * SS_STRIDE + cc] = val;
            }
        }
        __syncthreads();

        // Online softmax state update (one thread per row)
        if (tid < BQ) {
            int r = tid;
            float mold = m_s[r];
            float mt = -1e30f;
#pragma unroll 8
            for (int j = 0; j < BKV; ++j) mt = fmaxf(mt, Ss[r * SS_STRIDE + j]);
            float mnew = fmaxf(mold, mt);
            float sc = __expf(mold - mnew);
            float sum = 0.0f;
#pragma unroll 8
            for (int j = 0; j < BKV; ++j) {
                float e = __expf(Ss[r * SS_STRIDE + j] - mnew);
                Ss[r * SS_STRIDE + j] = e;
                sum += e;
            }
            l_s[r] = l_s[r] * sc + sum;
            m_s[r] = mnew;
            sc_s[r] = sc;
        }
        __syncthreads();

        // Rescale accumulator, then O += P * V
#pragma unroll
        for (int i = 0; i < 4; ++i) {
            float sc = sc_s[ty * 4 + i];
#pragma unroll
            for (int j = 0; j < 8; ++j) o[i][j] *= sc;
        }
#pragma unroll 4
        for (int k = 0; k < BKV; ++k) {
            float rp[4];
#pragma unroll
            for (int i = 0; i < 4; ++i) rp[i] = Ss[(ty * 4 + i) * SS_STRIDE + k];
            float4 v0 = *(const float4*)&Vs[k * HD + tx * 8];
            float4 v1 = *(const float4*)&Vs[k * HD + tx * 8 + 4];
            float rv[8] = {v0.x, v0.y, v0.z, v0.w, v1.x, v1.y, v1.z, v1.w};
#pragma unroll
            for (int i = 0; i < 4; ++i)
#pragma unroll
                for (int j = 0; j < 8; ++j)
                    o[i][j] = fmaf(rp[i], rv[j], o[i][j]);
        }
        __syncthreads();
    }

    // Write normalized output: layout (b, s, h*HD + d)
    float* Og = (float*)O + head_base + (size_t)(qt * BQ) * DIM;
#pragma unroll
    for (int i = 0; i < 4; ++i) {
        float inv = 1.0f / l_s[ty * 4 + i];
        float4 c0 = make_float4(o[i][0] * inv, o[i][1] * inv, o[i][2] * inv, o[i][3] * inv);
        float4 c1 = make_float4(o[i][4] * inv, o[i][5] * inv, o[i][6] * inv, o[i][7] * inv);
        *(float4*)&Og[(size_t)(ty * 4 + i) * DIM + tx * 8] = c0;
        *(float4*)&Og[(size_t)(ty * 4 + i) * DIM + tx * 8 + 4] = c1;
    }
}

// ---------------------------------------------------------------------------
// Launch
// Inputs: 0=x, 1=start_pos, 2=freqs_cos, 3=freqs_sin, 4=mask, 5=wq, 6=wk,
//         7=wv, 8=wo. Output: (B, S, DIM) fp32.
// ---------------------------------------------------------------------------
extern "C" void kernel_launch(void* const* d_in, const int* in_sizes, int n_in,
                              void* d_out, int out_size)
{
    const float* x  = (const float*)d_in[0];
    const float* fc = (const float*)d_in[2];
    const float* fs = (const float*)d_in[3];
    const float* wq = (const float*)d_in[5];
    const float* wk = (const float*)d_in[6];
    const float* wv = (const float*)d_in[7];
    const float* wo = (const float*)d_in[8];
    float* out = (float*)d_out;

    float *qp, *kp, *vp, *ap;
    cudaGetSymbolAddress((void**)&qp, g_q);
    cudaGetSymbolAddress((void**)&kp, g_k);
    cudaGetSymbolAddress((void**)&vp, g_v);
    cudaGetSymbolAddress((void**)&ap, g_att);

    dim3 gg(DIM / 128, MROWS / 128);   // (16, 32)

    gemm_nt_kernel<<<gg, 256>>>(x, wq, qp, MROWS, DIM, DIM);
    gemm_nt_kernel<<<gg, 256>>>(x, wk, kp, MROWS, DIM, DIM);
    gemm_nt_kernel<<<gg, 256>>>(x, wv, vp, MROWS, DIM, DIM);

    const int pairs = BSZ * SEQLEN * NH * (HD / 2);
    rope_kernel<<<pairs / 256, 256>>>(qp, kp, fc, fs);

    cudaFuncSetAttribute(flash_kernel,
                         cudaFuncAttributeMaxDynamicSharedMemorySize,
                         FLASH_SMEM_BYTES);
    dim3 fg(SEQLEN / BQ, BSZ * NH);    // (32, 32)
    flash_kernel<<<fg, 256, FLASH_SMEM_BYTES>>>(qp, kp, vp, ap);

    gemm_nt_kernel<<<gg, 256>>>(ap, wo, out, MROWS, DIM, DIM);
}

// round 4
// speedup vs baseline: 1.8334x; 1.8334x over previous
#include <cuda_runtime.h>
#include <cuda_bf16.h>
#include <cstdint>
#include <math.h>

#define DIM 2048
#define NH 16
#define HD 128
#define BSZ 2
#define SEQLEN 2048
#define MROWS (BSZ * SEQLEN)

// Scratch (static device arrays — allocation-free per harness rules)
__device__ float g_q[(size_t)MROWS * DIM];
__device__ float g_k[(size_t)MROWS * DIM];
__device__ float g_v[(size_t)MROWS * DIM];
__device__ float g_att[(size_t)MROWS * DIM];

__device__ __forceinline__ uint32_t f2tf32(float x) {
    uint32_t r;
    asm("cvt.rna.tf32.f32 %0, %1;" : "=r"(r) : "f"(x));
    return r;
}

__device__ __forceinline__ void mma_tf32(float* c, const uint32_t* a,
                                         const uint32_t* b) {
    asm volatile(
        "mma.sync.aligned.m16n8k8.row.col.f32.tf32.tf32.f32 "
        "{%0,%1,%2,%3}, {%4,%5,%6,%7}, {%8,%9}, {%0,%1,%2,%3};"
        : "+f"(c[0]), "+f"(c[1]), "+f"(c[2]), "+f"(c[3])
        : "r"(a[0]), "r"(a[1]), "r"(a[2]), "r"(a[3]), "r"(b[0]), "r"(b[1]));
}

// ===========================================================================
// tf32 mma.sync GEMM: C[M][N] = sum_k A[m][k]*B[n][k]  (NT, fp32 in/out)
// 128x128x32 block tile, 8 warps (2x4), warp tile 64x32, double-buffered smem.
// ===========================================================================
#define GBM 128
#define GBN 128
#define GBK 32
#define GST 36                     // smem row stride (floats): bank-conflict-free
#define GT_FLOATS (GBM * GST)      // one A (or B) tile
#define GBUF_FLOATS (2 * GT_FLOATS)
#define GEMM_SMEM (2 * GBUF_FLOATS * 4)   // 73728 bytes

__global__ __launch_bounds__(256) void gemm_mma_kernel(
    const float* __restrict__ A, const float* __restrict__ B,
    float* __restrict__ C, int M, int N, int K)
{
    extern __shared__ uint32_t smem[];   // [buf][A|B][128][36]
    const int tid = threadIdx.x;
    const int wid = tid >> 5;
    const int lane = tid & 31;
    const int warp_m = wid >> 2;         // 0..1
    const int warp_n = wid & 3;          // 0..3
    const int bm = blockIdx.y * GBM;
    const int bn = blockIdx.x * GBN;

    float acc[4][4][4];
#pragma unroll
    for (int i = 0; i < 4; ++i)
#pragma unroll
        for (int j = 0; j < 4; ++j)
#pragma unroll
            for (int r = 0; r < 4; ++r) acc[i][j][r] = 0.0f;

    // loader lambdas: each thread moves 4 float4 of A and 4 of B per stage
    float4 ra[4], rb[4];
    auto ldg_stage = [&](int k0) {
#pragma unroll
        for (int i = 0; i < 4; ++i) {
            int e = tid + i * 256;          // 0..1023
            int r = e >> 3;                 // 0..127
            int c = e & 7;                  // 0..7
            ra[i] = *(const float4*)(A + (size_t)(bm + r) * K + k0 + c * 4);
            rb[i] = *(const float4*)(B + (size_t)(bn + r) * K + k0 + c * 4);
        }
    };
    auto sts_stage = [&](int buf) {
        uint32_t* Asm = smem + buf * GBUF_FLOATS;
        uint32_t* Bsm = Asm + GT_FLOATS;
#pragma unroll
        for (int i = 0; i < 4; ++i) {
            int e = tid + i * 256;
            int r = e >> 3;
            int c = e & 7;
            uint4 ta = make_uint4(f2tf32(ra[i].x), f2tf32(ra[i].y),
                                  f2tf32(ra[i].z), f2tf32(ra[i].w));
            *(uint4*)(Asm + r * GST + c * 4) = ta;
            uint4 tb = make_uint4(f2tf32(rb[i].x), f2tf32(rb[i].y),
                                  f2tf32(rb[i].z), f2tf32(rb[i].w));
            *(uint4*)(Bsm + r * GST + c * 4) = tb;
        }
    };

    ldg_stage(0);
    sts_stage(0);
    __syncthreads();

    const int NSTAGE = K / GBK;   // 64
    for (int s = 0; s < NSTAGE; ++s) {
        const int buf = s & 1;
        if (s + 1 < NSTAGE) ldg_stage((s + 1) * GBK);

        const uint32_t* Asm = smem + buf * GBUF_FLOATS;
        const uint32_t* Bsm = Asm + GT_FLOATS;
        const int arow = warp_m * 64 + (lane >> 2);
        const int brow = warp_n * 32 + (lane >> 2);
        const int kc = lane & 3;

#pragma unroll
        for (int ks = 0; ks < 4; ++ks) {
            uint32_t af[4][4];
#pragma unroll
            for (int mt = 0; mt < 4; ++mt) {
                const uint32_t* p = Asm + (arow + mt * 16) * GST + ks * 8 + kc;
                af[mt][0] = p[0];
                af[mt][1] = p[8 * GST];
                af[mt][2] = p[4];
                af[mt][3] = p[8 * GST + 4];
            }
            uint32_t bf[4][2];
#pragma unroll
            for (int nt = 0; nt < 4; ++nt) {
                const uint32_t* p = Bsm + (brow + nt * 8) * GST + ks * 8 + kc;
                bf[nt][0] = p[0];
                bf[nt][1] = p[4];
            }
#pragma unroll
            for (int mt = 0; mt < 4; ++mt)
#pragma unroll
                for (int nt = 0; nt < 4; ++nt)
                    mma_tf32(acc[mt][nt], af[mt], bf[nt]);
        }

        if (s + 1 < NSTAGE) sts_stage(buf ^ 1);
        __syncthreads();
    }

    // epilogue
#pragma unroll
    for (int mt = 0; mt < 4; ++mt) {
        const int row0 = bm + warp_m * 64 + mt * 16 + (lane >> 2);
#pragma unroll
        for (int nt = 0; nt < 4; ++nt) {
            const int col = bn + warp_n * 32 + nt * 8 + (lane & 3) * 2;
            *(float2*)(C + (size_t)row0 * N + col) =
                make_float2(acc[mt][nt][0], acc[mt][nt][1]);
            *(float2*)(C + (size_t)(row0 + 8) * N + col) =
                make_float2(acc[mt][nt][2], acc[mt][nt][3]);
        }
    }
}

// ---------------------------------------------------------------------------
// RoPE (interleaved pairs), applied in-place to Q and K. start_pos = 0.
// ---------------------------------------------------------------------------
__global__ __launch_bounds__(256) void rope_kernel(
    float* __restrict__ q, float* __restrict__ k,
    const float* __restrict__ cosf, const float* __restrict__ sinf)
{
    int i = blockIdx.x * blockDim.x + threadIdx.x;   // pair index
    const int total = BSZ * SEQLEN * NH * (HD / 2);
    if (i >= total) return;
    int p = i & 63;
    int hh = (i >> 6) & 15;
    int s = (i >> 10) & 2047;
    int bb = i >> 21;
    size_t addr = ((size_t)(bb * SEQLEN + s)) * DIM + hh * HD + 2 * p;
    float c = cosf[s * 64 + p];
    float sn = sinf[s * 64 + p];
    float a = q[addr], b2 = q[addr + 1];
    q[addr]     = a * c - b2 * sn;
    q[addr + 1] = a * sn + b2 * c;
    a = k[addr]; b2 = k[addr + 1];
    k[addr]     = a * c - b2 * sn;
    k[addr + 1] = a * sn + b2 * c;
}

// ---------------------------------------------------------------------------
// Flash attention (fp32, causal). BQ = BKV = 64, 256 threads. (unchanged)
// ---------------------------------------------------------------------------
#define BQ 64
#define BKV 64
#define QS_STRIDE 65
#define SS_STRIDE 65
#define FLASH_SMEM_FLOATS (2 * HD * QS_STRIDE + BKV * HD + BQ * SS_STRIDE + 3 * BQ)
#define FLASH_SMEM_BYTES (FLASH_SMEM_FLOATS * 4)

__global__ __launch_bounds__(256) void flash_kernel(
    const float* __restrict__ Q, const float* __restrict__ K,
    const float* __restrict__ V, float* __restrict__ O)
{
    extern __shared__ float sm[];
    float* Qs = sm;                      // [HD][65]  (transposed: [d][m])
    float* Ks = Qs + HD * QS_STRIDE;     // [HD][65]
    float* Vs = Ks + HD * QS_STRIDE;     // [BKV][HD]
    float* Ss = Vs + BKV * HD;           // [BQ][65]
    float* m_s = Ss + BQ * SS_STRIDE;
    float* l_s = m_s + BQ;
    float* sc_s = l_s + BQ;

    const int qt = (int)gridDim.x - 1 - (int)blockIdx.x;  // heavy tiles first
    const int bh = blockIdx.y;
    const int b = bh >> 4;
    const int h = bh & 15;
    const int tid = threadIdx.x;
    const int ty = tid >> 4;
    const int tx = tid & 15;

    const size_t head_base = (size_t)b * SEQLEN * DIM + (size_t)h * HD;
    const float* Qg = Q + head_base + (size_t)(qt * BQ) * DIM;

#pragma unroll
    for (int it = 0; it < 8; ++it) {
        int idx = tid + it * 256;
        int m = idx >> 5;
        int d4 = (idx & 31) << 2;
        float4 v4 = *(const float4*)(Qg + (size_t)m * DIM + d4);
        Qs[(d4 + 0) * QS_STRIDE + m] = v4.x;
        Qs[(d4 + 1) * QS_STRIDE + m] = v4.y;
        Qs[(d4 + 2) * QS_STRIDE + m] = v4.z;
        Qs[(d4 + 3) * QS_STRIDE + m] = v4.w;
    }
    if (tid < BQ) { m_s[tid] = -1e30f; l_s[tid] = 0.0f; }

    float o[4][8];
#pragma unroll
    for (int i = 0; i < 4; ++i)
#pragma unroll
        for (int j = 0; j < 8; ++j) o[i][j] = 0.0f;

    __syncthreads();

    const float scale = 0.08838834764831845f;  // 1/sqrt(128)
    const int ntiles = qt + 1;
    for (int kt = 0; kt < ntiles; ++kt) {
        const float* Kg = K + head_base + (size_t)(kt * BKV) * DIM;
        const float* Vg = V + head_base + (size_t)(kt * BKV) * DIM;
#pragma unroll
        for (int it = 0; it < 8; ++it) {
            int idx = tid + it * 256;
            int m = idx >> 5;
            int d4 = (idx & 31) << 2;
            float4 kv4 = *(const float4*)(Kg + (size_t)m * DIM + d4);
            Ks[(d4 + 0) * QS_STRIDE + m] = kv4.x;
            Ks[(d4 + 1) * QS_STRIDE + m] = kv4.y;
            Ks[(d4 + 2) * QS_STRIDE + m] = kv4.z;
            Ks[(d4 + 3) * QS_STRIDE + m] = kv4.w;
            float4 vv4 = *(const float4*)(Vg + (size_t)m * DIM + d4);
            *(float4*)&Vs[m * HD + d4] = vv4;
        }
        __syncthreads();

        float s[4][4];
#pragma unroll
        for (int i = 0; i < 4; ++i)
#pragma unroll
            for (int j = 0; j < 4; ++j) s[i][j] = 0.0f;

#pragma unroll 4
        for (int d = 0; d < HD; ++d) {
            float ra[4], rb[4];
#pragma unroll
            for (int i = 0; i < 4; ++i) ra[i] = Qs[d * QS_STRIDE + ty * 4 + i];
#pragma unroll
            for (int j = 0; j < 4; ++j) rb[j] = Ks[d * QS_STRIDE + tx * 4 + j];
#pragma unroll
            for (int i = 0; i < 4; ++i)
#pragma unroll
                for (int j = 0; j < 4; ++j)
                    s[i][j] = fmaf(ra[i], rb[j], s[i][j]);
        }

        const bool diag = (kt == qt);
#pragma unroll
        for (int i = 0; i < 4; ++i) {
            int rr = ty * 4 + i;
#pragma unroll
            for (int j = 0; j < 4; ++j) {
                int cc = tx * 4 + j;
                float val = s[i][j] * scale;
                if (diag && cc > rr) val = -1e30f;
                Ss[rr * SS_STRIDE + cc] = val;
            }
        }
        __syncthreads();

        if (tid < BQ) {
            int r = tid;
            float mold = m_s[r];
            float mt = -1e30f;
#pragma unroll 8
            for (int j = 0; j < BKV; ++j) mt = fmaxf(mt, Ss[r * SS_STRIDE + j]);
            float mnew = fmaxf(mold, mt);
            float sc = __expf(mold - mnew);
            float sum = 0.0f;
#pragma unroll 8
            for (int j = 0; j < BKV; ++j) {
                float e = __expf(Ss[r * SS_STRIDE + j] - mnew);
                Ss[r * SS_STRIDE + j] = e;
                sum += e;
            }
            l_s[r] = l_s[r] * sc + sum;
            m_s[r] = mnew;
            sc_s[r] = sc;
        }
        __syncthreads();

#pragma unroll
        for (int i = 0; i < 4; ++i) {
            float sc = sc_s[ty * 4 + i];
#pragma unroll
            for (int j = 0; j < 8; ++j) o[i][j] *= sc;
        }
#pragma unroll 4
        for (int k = 0; k < BKV; ++k) {
            float rp[4];
#pragma unroll
            for (int i = 0; i < 4; ++i) rp[i] = Ss[(ty * 4 + i) * SS_STRIDE + k];
            float4 v0 = *(const float4*)&Vs[k * HD + tx * 8];
            float4 v1 = *(const float4*)&Vs[k * HD + tx * 8 + 4];
            float rv[8] = {v0.x, v0.y, v0.z, v0.w, v1.x, v1.y, v1.z, v1.w};
#pragma unroll
            for (int i = 0; i < 4; ++i)
#pragma unroll
                for (int j = 0; j < 8; ++j)
                    o[i][j] = fmaf(rp[i], rv[j], o[i][j]);
        }
        __syncthreads();
    }

    float* Og = (float*)O + head_base + (size_t)(qt * BQ) * DIM;
#pragma unroll
    for (int i = 0; i < 4; ++i) {
        float inv = 1.0f / l_s[ty * 4 + i];
        float4 c0 = make_float4(o[i][0] * inv, o[i][1] * inv, o[i][2] * inv, o[i][3] * inv);
        float4 c1 = make_float4(o[i][4] * inv, o[i][5] * inv, o[i][6] * inv, o[i][7] * inv);
        *(float4*)&Og[(size_t)(ty * 4 + i) * DIM + tx * 8] = c0;
        *(float4*)&Og[(size_t)(ty * 4 + i) * DIM + tx * 8 + 4] = c1;
    }
}

// ---------------------------------------------------------------------------
// Launch. Inputs: 0=x, 1=start_pos, 2=freqs_cos, 3=freqs_sin, 4=mask,
// 5=wq, 6=wk, 7=wv, 8=wo. Output: (B, S, DIM) fp32.
// ---------------------------------------------------------------------------
extern "C" void kernel_launch(void* const* d_in, const int* in_sizes, int n_in,
                              void* d_out, int out_size)
{
    const float* x  = (const float*)d_in[0];
    const float* fc = (const float*)d_in[2];
    const float* fs = (const float*)d_in[3];
    const float* wq = (const float*)d_in[5];
    const float* wk = (const float*)d_in[6];
    const float* wv = (const float*)d_in[7];
    const float* wo = (const float*)d_in[8];
    float* out = (float*)d_out;

    float *qp, *kp, *vp, *ap;
    cudaGetSymbolAddress((void**)&qp, g_q);
    cudaGetSymbolAddress((void**)&kp, g_k);
    cudaGetSymbolAddress((void**)&vp, g_v);
    cudaGetSymbolAddress((void**)&ap, g_att);

    cudaFuncSetAttribute(gemm_mma_kernel,
                         cudaFuncAttributeMaxDynamicSharedMemorySize, GEMM_SMEM);
    dim3 gg(DIM / GBN, MROWS / GBM);   // (16, 32)

    gemm_mma_kernel<<<gg, 256, GEMM_SMEM>>>(x, wq, qp, MROWS, DIM, DIM);
    gemm_mma_kernel<<<gg, 256, GEMM_SMEM>>>(x, wk, kp, MROWS, DIM, DIM);
    gemm_mma_kernel<<<gg, 256, GEMM_SMEM>>>(x, wv, vp, MROWS, DIM, DIM);

    const int pairs = BSZ * SEQLEN * NH * (HD / 2);
    rope_kernel<<<pairs / 256, 256>>>(qp, kp, fc, fs);

    cudaFuncSetAttribute(flash_kernel,
                         cudaFuncAttributeMaxDynamicSharedMemorySize,
                         FLASH_SMEM_BYTES);
    dim3 fg(SEQLEN / BQ, BSZ * NH);    // (32, 32)
    flash_kernel<<<fg, 256, FLASH_SMEM_BYTES>>>(qp, kp, vp, ap);

    gemm_mma_kernel<<<gg, 256, GEMM_SMEM>>>(ap, wo, out, MROWS, DIM, DIM);
}

// round 5
// speedup vs baseline: 3.1009x; 1.6913x over previous
#include <cuda_runtime.h>
#include <cuda_bf16.h>
#include <cstdint>
#include <math.h>

#define DIM 2048
#define NH 16
#define HD 128
#define BSZ 2
#define SEQLEN 2048
#define MROWS (BSZ * SEQLEN)

// Scratch (static device arrays — allocation-free per harness rules)
__device__ float g_q[(size_t)MROWS * DIM];
__device__ float g_k[(size_t)MROWS * DIM];
__device__ float g_v[(size_t)MROWS * DIM];
__device__ float g_att[(size_t)MROWS * DIM];

__device__ __forceinline__ uint32_t f2tf32(float x) {
    uint32_t r;
    asm("cvt.rna.tf32.f32 %0, %1;" : "=r"(r) : "f"(x));
    return r;
}

__device__ __forceinline__ void mma_tf32(float* c, const uint32_t* a,
                                         const uint32_t* b) {
    asm volatile(
        "mma.sync.aligned.m16n8k8.row.col.f32.tf32.tf32.f32 "
        "{%0,%1,%2,%3}, {%4,%5,%6,%7}, {%8,%9}, {%0,%1,%2,%3};"
        : "+f"(c[0]), "+f"(c[1]), "+f"(c[2]), "+f"(c[3])
        : "r"(a[0]), "r"(a[1]), "r"(a[2]), "r"(a[3]), "r"(b[0]), "r"(b[1]));
}

__device__ __forceinline__ uint32_t smem_u32(const void* p) {
    uint32_t a;
    asm("{ .reg .u64 t; cvta.to.shared.u64 t, %1; cvt.u32.u64 %0, t; }"
        : "=r"(a) : "l"(p));
    return a;
}
__device__ __forceinline__ void cp_async16(uint32_t dst, const void* src) {
    asm volatile("cp.async.cg.shared.global [%0], [%1], 16;"
                 :: "r"(dst), "l"(src) : "memory");
}
#define CP_COMMIT() asm volatile("cp.async.commit_group;" ::: "memory")
#define CP_WAIT(N)  asm volatile("cp.async.wait_group %0;" :: "n"(N) : "memory")

// ===========================================================================
// tf32 mma.sync GEMM: C[M][N] = sum_k A[m][k]*B[n][k]  (NT, fp32 in/out)
// ===========================================================================
#define GBM 128
#define GBN 128
#define GBK 32
#define GST 36
#define GT_FLOATS (GBM * GST)
#define GBUF_FLOATS (2 * GT_FLOATS)
#define GEMM_SMEM (2 * GBUF_FLOATS * 4)   // 73728 bytes

__global__ __launch_bounds__(256) void gemm_mma_kernel(
    const float* __restrict__ A, const float* __restrict__ B,
    float* __restrict__ C, int M, int N, int K)
{
    extern __shared__ uint32_t smem[];
    const int tid = threadIdx.x;
    const int wid = tid >> 5;
    const int lane = tid & 31;
    const int warp_m = wid >> 2;
    const int warp_n = wid & 3;
    const int bm = blockIdx.y * GBM;
    const int bn = blockIdx.x * GBN;

    float acc[4][4][4];
#pragma unroll
    for (int i = 0; i < 4; ++i)
#pragma unroll
        for (int j = 0; j < 4; ++j)
#pragma unroll
            for (int r = 0; r < 4; ++r) acc[i][j][r] = 0.0f;

    float4 ra[4], rb[4];
    auto ldg_stage = [&](int k0) {
#pragma unroll
        for (int i = 0; i < 4; ++i) {
            int e = tid + i * 256;
            int r = e >> 3;
            int c = e & 7;
            ra[i] = *(const float4*)(A + (size_t)(bm + r) * K + k0 + c * 4);
            rb[i] = *(const float4*)(B + (size_t)(bn + r) * K + k0 + c * 4);
        }
    };
    auto sts_stage = [&](int buf) {
        uint32_t* Asm = smem + buf * GBUF_FLOATS;
        uint32_t* Bsm = Asm + GT_FLOATS;
#pragma unroll
        for (int i = 0; i < 4; ++i) {
            int e = tid + i * 256;
            int r = e >> 3;
            int c = e & 7;
            uint4 ta = make_uint4(f2tf32(ra[i].x), f2tf32(ra[i].y),
                                  f2tf32(ra[i].z), f2tf32(ra[i].w));
            *(uint4*)(Asm + r * GST + c * 4) = ta;
            uint4 tb = make_uint4(f2tf32(rb[i].x), f2tf32(rb[i].y),
                                  f2tf32(rb[i].z), f2tf32(rb[i].w));
            *(uint4*)(Bsm + r * GST + c * 4) = tb;
        }
    };

    ldg_stage(0);
    sts_stage(0);
    __syncthreads();

    const int NSTAGE = K / GBK;
    for (int s = 0; s < NSTAGE; ++s) {
        const int buf = s & 1;
        if (s + 1 < NSTAGE) ldg_stage((s + 1) * GBK);

        const uint32_t* Asm = smem + buf * GBUF_FLOATS;
        const uint32_t* Bsm = Asm + GT_FLOATS;
        const int arow = warp_m * 64 + (lane >> 2);
        const int brow = warp_n * 32 + (lane >> 2);
        const int kc = lane & 3;

#pragma unroll
        for (int ks = 0; ks < 4; ++ks) {
            uint32_t af[4][4];
#pragma unroll
            for (int mt = 0; mt < 4; ++mt) {
                const uint32_t* p = Asm + (arow + mt * 16) * GST + ks * 8 + kc;
                af[mt][0] = p[0];
                af[mt][1] = p[8 * GST];
                af[mt][2] = p[4];
                af[mt][3] = p[8 * GST + 4];
            }
            uint32_t bf[4][2];
#pragma unroll
            for (int nt = 0; nt < 4; ++nt) {
                const uint32_t* p = Bsm + (brow + nt * 8) * GST + ks * 8 + kc;
                bf[nt][0] = p[0];
                bf[nt][1] = p[4];
            }
#pragma unroll
            for (int mt = 0; mt < 4; ++mt)
#pragma unroll
                for (int nt = 0; nt < 4; ++nt)
                    mma_tf32(acc[mt][nt], af[mt], bf[nt]);
        }

        if (s + 1 < NSTAGE) sts_stage(buf ^ 1);
        __syncthreads();
    }

#pragma unroll
    for (int mt = 0; mt < 4; ++mt) {
        const int row0 = bm + warp_m * 64 + mt * 16 + (lane >> 2);
#pragma unroll
        for (int nt = 0; nt < 4; ++nt) {
            const int col = bn + warp_n * 32 + nt * 8 + (lane & 3) * 2;
            *(float2*)(C + (size_t)row0 * N + col) =
                make_float2(acc[mt][nt][0], acc[mt][nt][1]);
            *(float2*)(C + (size_t)(row0 + 8) * N + col) =
                make_float2(acc[mt][nt][2], acc[mt][nt][3]);
        }
    }
}

// ---------------------------------------------------------------------------
// RoPE (interleaved pairs), in-place on Q and K. start_pos = 0.
// ---------------------------------------------------------------------------
__global__ __launch_bounds__(256) void rope_kernel(
    float* __restrict__ q, float* __restrict__ k,
    const float* __restrict__ cosf, const float* __restrict__ sinf)
{
    int i = blockIdx.x * blockDim.x + threadIdx.x;
    const int total = BSZ * SEQLEN * NH * (HD / 2);
    if (i >= total) return;
    int p = i & 63;
    int hh = (i >> 6) & 15;
    int s = (i >> 10) & 2047;
    int bb = i >> 21;
    size_t addr = ((size_t)(bb * SEQLEN + s)) * DIM + hh * HD + 2 * p;
    float c = cosf[s * 64 + p];
    float sn = sinf[s * 64 + p];
    float a = q[addr], b2 = q[addr + 1];
    q[addr]     = a * c - b2 * sn;
    q[addr + 1] = a * sn + b2 * c;
    a = k[addr]; b2 = k[addr + 1];
    k[addr]     = a * c - b2 * sn;
    k[addr + 1] = a * sn + b2 * c;
}

// ===========================================================================
// Flash attention, tf32 mma.sync. BQ=BKV=64, 256 threads (8 warps).
// QK^T: warp tile 16x32 (warp_m=wid>>1, warp_n=wid&1). PV: warp tile 16x64.
// K/V double-buffered via cp.async. P written in-place over S as tf32 bits.
// ===========================================================================
#define BQ 64
#define BKV 64
#define FQ_ST 132          // Q smem stride (floats): (4r+c)%32 conflict-free
#define FK_ST 132
#define FV_ST 136          // V stride: (8k+n)%32 conflict-free for B-frag
#define FS_ST 68

#define OFF_Q  0
#define OFF_K  (OFF_Q + BQ * FQ_ST)                 // 8448
#define OFF_V  (OFF_K + 2 * BKV * FK_ST)            // 8448 + 16896
#define OFF_S  (OFF_V + 2 * BKV * FV_ST)            // + 17408
#define OFF_RED (OFF_S + BQ * FS_ST)
#define OFF_M  (OFF_RED + 256)
#define OFF_L  (OFF_M + BQ)
#define OFF_SC (OFF_L + BQ)
#define FLASH_SMEM_FLOATS (OFF_SC + BQ)
#define FLASH_SMEM_BYTES (FLASH_SMEM_FLOATS * 4)    // ~190KB

__global__ __launch_bounds__(256) void flash_kernel(
    const float* __restrict__ Q, const float* __restrict__ K,
    const float* __restrict__ V, float* __restrict__ O)
{
    extern __shared__ float sm[];
    uint32_t* smu = (uint32_t*)sm;
    float* Ks = sm + OFF_K;
    float* Vs = sm + OFF_V;
    uint32_t* Qs = smu + OFF_Q;
    uint32_t* Ss = smu + OFF_S;
    float* red = sm + OFF_RED;
    float* m_s = sm + OFF_M;
    float* l_s = sm + OFF_L;
    float* sc_s = sm + OFF_SC;

    const int qt = (int)gridDim.x - 1 - (int)blockIdx.x;   // heavy tiles first
    const int bh = blockIdx.y;
    const int b = bh >> 4;
    const int h = bh & 15;
    const int tid = threadIdx.x;
    const int wid = tid >> 5;
    const int lane = tid & 31;
    const int warp_m = wid >> 1;     // 0..3
    const int warp_n = wid & 1;      // 0..1
    const int lr = lane >> 2;        // 0..7
    const int kc = lane & 3;         // 0..3

    const size_t head_base = (size_t)b * SEQLEN * DIM + (size_t)h * HD;
    const float* Qg = Q + head_base + (size_t)(qt * BQ) * DIM;
    const float scale = 0.08838834764831845f;   // 1/sqrt(128)

    // Load Q (scale folded, converted to tf32 once)
#pragma unroll
    for (int i = 0; i < 8; ++i) {
        int e = tid + i * 256;
        int r = e >> 5;
        int c = (e & 31) << 2;
        float4 v4 = *(const float4*)(Qg + (size_t)r * DIM + c);
        Qs[r * FQ_ST + c + 0] = f2tf32(v4.x * scale);
        Qs[r * FQ_ST + c + 1] = f2tf32(v4.y * scale);
        Qs[r * FQ_ST + c + 2] = f2tf32(v4.z * scale);
        Qs[r * FQ_ST + c + 3] = f2tf32(v4.w * scale);
    }
    if (tid < BQ) { m_s[tid] = -1e30f; l_s[tid] = 0.0f; }

    float accO[8][4];
#pragma unroll
    for (int i = 0; i < 8; ++i)
#pragma unroll
        for (int r = 0; r < 4; ++r) accO[i][r] = 0.0f;

    const uint32_t k_su = smem_u32(Ks);
    const uint32_t v_su = smem_u32(Vs);
    auto prefetch = [&](int kt, int buf) {
        const float* Kg = K + head_base + (size_t)(kt * BKV) * DIM;
        const float* Vg = V + head_base + (size_t)(kt * BKV) * DIM;
        const uint32_t kb = k_su + buf * (BKV * FK_ST * 4);
        const uint32_t vb = v_su + buf * (BKV * FV_ST * 4);
#pragma unroll
        for (int i = 0; i < 8; ++i) {
            int e = tid + i * 256;
            int r = e >> 5;
            int c = (e & 31) << 2;
            cp_async16(kb + (r * FK_ST + c) * 4, Kg + (size_t)r * DIM + c);
            cp_async16(vb + (r * FV_ST + c) * 4, Vg + (size_t)r * DIM + c);
        }
        CP_COMMIT();
    };

    prefetch(0, 0);
    __syncthreads();   // Q visible (and m/l init)

    const int ntiles = qt + 1;
    for (int kt = 0; kt < ntiles; ++kt) {
        const int buf = kt & 1;
        const bool more = (kt + 1 < ntiles);
        if (more) prefetch(kt + 1, buf ^ 1);
        if (more) { CP_WAIT(1); } else { CP_WAIT(0); }
        __syncthreads();

        // ---- QK^T: 16x32 warp tile ----
        float accS[4][4];
#pragma unroll
        for (int nf = 0; nf < 4; ++nf)
#pragma unroll
            for (int r = 0; r < 4; ++r) accS[nf][r] = 0.0f;

        const uint32_t* Qw = Qs + (warp_m * 16 + lr) * FQ_ST + kc;
        const float* Kw = Ks + (size_t)buf * (BKV * FK_ST) +
                          (warp_n * 32 + lr) * FK_ST + kc;
#pragma unroll
        for (int ks = 0; ks < 16; ++ks) {
            uint32_t a[4];
            const uint32_t* ap = Qw + ks * 8;
            a[0] = ap[0];
            a[1] = ap[8 * FQ_ST];
            a[2] = ap[4];
            a[3] = ap[8 * FQ_ST + 4];
#pragma unroll
            for (int nf = 0; nf < 4; ++nf) {
                const float* bp = Kw + nf * 8 * FK_ST + ks * 8;
                uint32_t bfr[2];
                bfr[0] = f2tf32(bp[0]);
                bfr[1] = f2tf32(bp[4]);
                mma_tf32(accS[nf], a, bfr);
            }
        }

        // ---- store scores (mask on diagonal tile) ----
        const bool diag = (kt == qt);
        const int r0 = warp_m * 16 + lr;
#pragma unroll
        for (int nf = 0; nf < 4; ++nf) {
            int cb = warp_n * 32 + nf * 8 + kc * 2;
            float v0 = accS[nf][0], v1 = accS[nf][1];
            float v2 = accS[nf][2], v3 = accS[nf][3];
            if (diag) {
                if (cb > r0)      v0 = -1e30f;
                if (cb + 1 > r0)  v1 = -1e30f;
                if (cb > r0 + 8)     v2 = -1e30f;
                if (cb + 1 > r0 + 8) v3 = -1e30f;
            }
            Ss[r0 * FS_ST + cb]           = __float_as_uint(v0);
            Ss[r0 * FS_ST + cb + 1]       = __float_as_uint(v1);
            Ss[(r0 + 8) * FS_ST + cb]     = __float_as_uint(v2);
            Ss[(r0 + 8) * FS_ST + cb + 1] = __float_as_uint(v3);
        }
        __syncthreads();

        // ---- softmax: 4 threads per row, 16 cols each ----
        const int srow = tid & 63;
        const int sq = tid >> 6;           // 0..3
        {
            float mx = -1e30f;
#pragma unroll
            for (int j = 0; j < 16; ++j)
                mx = fmaxf(mx, __uint_as_float(Ss[srow * FS_ST + sq * 16 + j]));
            red[sq * 64 + srow] = mx;
        }
        __syncthreads();
        if (tid < BQ) {
            float mold = m_s[tid];
            float mt = fmaxf(fmaxf(red[tid], red[64 + tid]),
                             fmaxf(red[128 + tid], red[192 + tid]));
            float mnew = fmaxf(mold, mt);
            m_s[tid] = mnew;
            sc_s[tid] = __expf(mold - mnew);
        }
        __syncthreads();
        {
            float mnew = m_s[srow];
            float sum = 0.0f;
#pragma unroll
            for (int j = 0; j < 16; ++j) {
                int idx = srow * FS_ST + sq * 16 + j;
                float e = __expf(__uint_as_float(Ss[idx]) - mnew);
                Ss[idx] = f2tf32(e);
                sum += e;
            }
            red[sq * 64 + srow] = sum;
        }
        __syncthreads();
        if (tid < BQ) {
            l_s[tid] = l_s[tid] * sc_s[tid] +
                       (red[tid] + red[64 + tid] + red[128 + tid] + red[192 + tid]);
        }

        // ---- rescale O, then O += P @ V (16x64 warp tile) ----
        const float scr0 = sc_s[r0];
        const float scr1 = sc_s[r0 + 8];
#pragma unroll
        for (int nf = 0; nf < 8; ++nf) {
            accO[nf][0] *= scr0;
            accO[nf][1] *= scr0;
            accO[nf][2] *= scr1;
            accO[nf][3] *= scr1;
        }

        const uint32_t* Pw = Ss + (warp_m * 16 + lr) * FS_ST + kc;
        const float* Vw = Vs + (size_t)buf * (BKV * FV_ST) +
                          kc * FV_ST + warp_n * 64 + lr;
#pragma unroll
        for (int ks = 0; ks < 8; ++ks) {
            uint32_t a[4];
            const uint32_t* ap = Pw + ks * 8;
            a[0] = ap[0];
            a[1] = ap[8 * FS_ST];
            a[2] = ap[4];
            a[3] = ap[8 * FS_ST + 4];
            const float* bp = Vw + ks * 8 * FV_ST;
#pragma unroll
            for (int nf = 0; nf < 8; ++nf) {
                uint32_t bfr[2];
                bfr[0] = f2tf32(bp[nf * 8]);
                bfr[1] = f2tf32(bp[4 * FV_ST + nf * 8]);
                mma_tf32(accO[nf], a, bfr);
            }
        }
        __syncthreads();
    }

    // ---- normalize + write O ----
    const int row0 = warp_m * 16 + lr;
    const float inv0 = 1.0f / l_s[row0];
    const float inv1 = 1.0f / l_s[row0 + 8];
    float* Og = O + head_base + (size_t)(qt * BQ) * DIM;
#pragma unroll
    for (int nf = 0; nf < 8; ++nf) {
        int col = warp_n * 64 + nf * 8 + kc * 2;
        *(float2*)(Og + (size_t)row0 * DIM + col) =
            make_float2(accO[nf][0] * inv0, accO[nf][1] * inv0);
        *(float2*)(Og + (size_t)(row0 + 8) * DIM + col) =
            make_float2(accO[nf][2] * inv1, accO[nf][3] * inv1);
    }
}

// ---------------------------------------------------------------------------
// Launch. Inputs: 0=x, 1=start_pos, 2=freqs_cos, 3=freqs_sin, 4=mask,
// 5=wq, 6=wk, 7=wv, 8=wo. Output: (B, S, DIM) fp32.
// ---------------------------------------------------------------------------
extern "C" void kernel_launch(void* const* d_in, const int* in_sizes, int n_in,
                              void* d_out, int out_size)
{
    const float* x  = (const float*)d_in[0];
    const float* fc = (const float*)d_in[2];
    const float* fs = (const float*)d_in[3];
    const float* wq = (const float*)d_in[5];
    const float* wk = (const float*)d_in[6];
    const float* wv = (const float*)d_in[7];
    const float* wo = (const float*)d_in[8];
    float* out = (float*)d_out;

    float *qp, *kp, *vp, *ap;
    cudaGetSymbolAddress((void**)&qp, g_q);
    cudaGetSymbolAddress((void**)&kp, g_k);
    cudaGetSymbolAddress((void**)&vp, g_v);
    cudaGetSymbolAddress((void**)&ap, g_att);

    cudaFuncSetAttribute(gemm_mma_kernel,
                         cudaFuncAttributeMaxDynamicSharedMemorySize, GEMM_SMEM);
    dim3 gg(DIM / GBN, MROWS / GBM);   // (16, 32)

    gemm_mma_kernel<<<gg, 256, GEMM_SMEM>>>(x, wq, qp, MROWS, DIM, DIM);
    gemm_mma_kernel<<<gg, 256, GEMM_SMEM>>>(x, wk, kp, MROWS, DIM, DIM);
    gemm_mma_kernel<<<gg, 256, GEMM_SMEM>>>(x, wv, vp, MROWS, DIM, DIM);

    const int pairs = BSZ * SEQLEN * NH * (HD / 2);
    rope_kernel<<<pairs / 256, 256>>>(qp, kp, fc, fs);

    cudaFuncSetAttribute(flash_kernel,
                         cudaFuncAttributeMaxDynamicSharedMemorySize,
                         FLASH_SMEM_BYTES);
    dim3 fg(SEQLEN / BQ, BSZ * NH);    // (32, 32)
    flash_kernel<<<fg, 256, FLASH_SMEM_BYTES>>>(qp, kp, vp, ap);

    gemm_mma_kernel<<<gg, 256, GEMM_SMEM>>>(ap, wo, out, MROWS, DIM, DIM);
}

// round 7
// speedup vs baseline: 3.4651x; 1.1175x over previous
#include <cuda_runtime.h>
#include <cuda_bf16.h>
#include <cstdint>
#include <math.h>

#define DIM 2048
#define NH 16
#define HD 128
#define BSZ 2
#define SEQLEN 2048
#define MROWS (BSZ * SEQLEN)

// Scratch (static device arrays — allocation-free per harness rules)
__device__ float g_q[(size_t)MROWS * DIM];
__device__ float g_k[(size_t)MROWS * DIM];
__device__ float g_v[(size_t)MROWS * DIM];
__device__ float g_att[(size_t)MROWS * DIM];
__device__ uint32_t g_xt[(size_t)MROWS * DIM];
__device__ uint32_t g_wqt[(size_t)DIM * DIM];
__device__ uint32_t g_wkt[(size_t)DIM * DIM];
__device__ uint32_t g_wvt[(size_t)DIM * DIM];
__device__ uint32_t g_wot[(size_t)DIM * DIM];

__device__ __forceinline__ uint32_t f2tf32(float x) {
    uint32_t r;
    asm("cvt.rna.tf32.f32 %0, %1;" : "=r"(r) : "f"(x));
    return r;
}

__device__ __forceinline__ void mma_tf32(float* c, const uint32_t* a,
                                         const uint32_t* b) {
    asm volatile(
        "mma.sync.aligned.m16n8k8.row.col.f32.tf32.tf32.f32 "
        "{%0,%1,%2,%3}, {%4,%5,%6,%7}, {%8,%9}, {%0,%1,%2,%3};"
        : "+f"(c[0]), "+f"(c[1]), "+f"(c[2]), "+f"(c[3])
        : "r"(a[0]), "r"(a[1]), "r"(a[2]), "r"(a[3]), "r"(b[0]), "r"(b[1]));
}

__device__ __forceinline__ uint32_t smem_u32(const void* p) {
    uint32_t a;
    asm("{ .reg .u64 t; cvta.to.shared.u64 t, %1; cvt.u32.u64 %0, t; }"
        : "=r"(a) : "l"(p));
    return a;
}
__device__ __forceinline__ void cp_async16(uint32_t dst, const void* src) {
    asm volatile("cp.async.cg.shared.global [%0], [%1], 16;"
                 :: "r"(dst), "l"(src) : "memory");
}
#define CP_COMMIT() asm volatile("cp.async.commit_group;" ::: "memory")
#define CP_WAIT(N)  asm volatile("cp.async.wait_group %0;" :: "n"(N) : "memory")

// ---------------------------------------------------------------------------
// fp32 -> tf32-bits elementwise convert (vectorized)
// ---------------------------------------------------------------------------
__global__ __launch_bounds__(256) void cvt_tf32_kernel(
    const float4* __restrict__ in, uint4* __restrict__ out, int n4)
{
    int i = blockIdx.x * blockDim.x + threadIdx.x;
    if (i >= n4) return;
    float4 v = in[i];
    out[i] = make_uint4(f2tf32(v.x), f2tf32(v.y), f2tf32(v.z), f2tf32(v.w));
}

// ===========================================================================
// tf32 mma.sync GEMM on pre-converted tf32 bits. C = A * B^T.
// 128x128x32 block tile, 8 warps, 4-buffer depth-3 cp.async pipeline.
// grid.z selects (B, C) among up to 3; RoPE fused in epilogue when
// do_rope && z < 2 (rows are seq positions, col pairs are rope pairs).
// ===========================================================================
#define GBM 128
#define GBN 128
#define GBK 32
#define GST 36
#define GT_U32 (GBM * GST)                // one A (or B) stage tile
#define GSTAGE_U32 (2 * GT_U32)           // A + B
#define GEMM_SMEM (4 * GSTAGE_U32 * 4)    // 4 buffers = 147456 bytes
#define NSTAGE (DIM / GBK)                // 64

__global__ __launch_bounds__(256) void gemm_mma_kernel(
    const uint32_t* __restrict__ A,
    const uint32_t* __restrict__ B0, const uint32_t* __restrict__ B1,
    const uint32_t* __restrict__ B2,
    float* __restrict__ C0, float* __restrict__ C1, float* __restrict__ C2,
    const float* __restrict__ cosf, const float* __restrict__ sinf,
    int do_rope)
{
    extern __shared__ uint32_t smem[];
    const int tid = threadIdx.x;
    const int wid = tid >> 5;
    const int lane = tid & 31;
    const int warp_m = wid >> 2;
    const int warp_n = wid & 3;
    const int bm = blockIdx.y * GBM;
    const int bn = blockIdx.x * GBN;
    const int z = blockIdx.z;

    const uint32_t* B = (z == 0) ? B0 : (z == 1) ? B1 : B2;
    float* C = (z == 0) ? C0 : (z == 1) ? C1 : C2;
    const bool rope = do_rope && (z < 2);

    const uint32_t smem_base = smem_u32(smem);

    float acc[4][4][4];
#pragma unroll
    for (int i = 0; i < 4; ++i)
#pragma unroll
        for (int j = 0; j < 4; ++j)
#pragma unroll
            for (int r = 0; r < 4; ++r) acc[i][j][r] = 0.0f;

    // per-thread cp.async coords: 8 ld of 16B per stage (4 A + 4 B)
    const int pr = tid >> 3;        // 0..31  (row block of 4)
    const int pc = tid & 7;         // 0..7   (col group of 4 floats)
    auto prefetch = [&](int s) {
        const int k0 = s * GBK;
        const uint32_t sb = smem_base + (s & 3) * (GSTAGE_U32 * 4);
#pragma unroll
        for (int i = 0; i < 4; ++i) {
            int r = pr + i * 32;
            cp_async16(sb + (r * GST + pc * 4) * 4,
                       A + (size_t)(bm + r) * DIM + k0 + pc * 4);
            cp_async16(sb + (GT_U32 + r * GST + pc * 4) * 4,
                       B + (size_t)(bn + r) * DIM + k0 + pc * 4);
        }
        CP_COMMIT();
    };

    prefetch(0);
    prefetch(1);
    prefetch(2);

    const int arow = warp_m * 64 + (lane >> 2);
    const int brow = warp_n * 32 + (lane >> 2);
    const int kc = lane & 3;

    for (int s = 0; s < NSTAGE; ++s) {
        CP_WAIT(2);
        __syncthreads();
        if (s + 3 < NSTAGE) prefetch(s + 3);

        const uint32_t* Asm = smem + (s & 3) * GSTAGE_U32;
        const uint32_t* Bsm = Asm + GT_U32;

#pragma unroll
        for (int ks = 0; ks < 4; ++ks) {
            uint32_t af[4][4];
#pragma unroll
            for (int mt = 0; mt < 4; ++mt) {
                const uint32_t* p = Asm + (arow + mt * 16) * GST + ks * 8 + kc;
                af[mt][0] = p[0];
                af[mt][1] = p[8 * GST];
                af[mt][2] = p[4];
                af[mt][3] = p[8 * GST + 4];
            }
            uint32_t bf[4][2];
#pragma unroll
            for (int nt = 0; nt < 4; ++nt) {
                const uint32_t* p = Bsm + (brow + nt * 8) * GST + ks * 8 + kc;
                bf[nt][0] = p[0];
                bf[nt][1] = p[4];
            }
#pragma unroll
            for (int mt = 0; mt < 4; ++mt)
#pragma unroll
                for (int nt = 0; nt < 4; ++nt)
                    mma_tf32(acc[mt][nt], af[mt], bf[nt]);
        }
    }

    // epilogue (optionally fused RoPE: each float2 is one rope pair)
#pragma unroll
    for (int mt = 0; mt < 4; ++mt) {
        const int row0 = bm + warp_m * 64 + mt * 16 + (lane >> 2);
        const int s0 = row0 & (SEQLEN - 1);
#pragma unroll
        for (int nt = 0; nt < 4; ++nt) {
            const int col = bn + warp_n * 32 + nt * 8 + (lane & 3) * 2;
            float v0 = acc[mt][nt][0], v1 = acc[mt][nt][1];
            float v2 = acc[mt][nt][2], v3 = acc[mt][nt][3];
            if (rope) {
                const int p = (col & (HD - 1)) >> 1;
                float c0 = cosf[s0 * 64 + p], n0 = sinf[s0 * 64 + p];
                float c1 = cosf[(s0 + 8) * 64 + p], n1 = sinf[(s0 + 8) * 64 + p];
                float t0 = v0 * c0 - v1 * n0;
                v1 = v0 * n0 + v1 * c0; v0 = t0;
                float t2 = v2 * c1 - v3 * n1;
                v3 = v2 * n1 + v3 * c1; v2 = t2;
            }
            *(float2*)(C + (size_t)row0 * DIM + col) = make_float2(v0, v1);
            *(float2*)(C + (size_t)(row0 + 8) * DIM + col) = make_float2(v2, v3);
        }
    }
}

// ===========================================================================
// Flash attention, tf32 mma.sync. BQ=BKV=64, 256 threads (8 warps).
// Output written tf32-rounded so the wo GEMM can consume it as tf32 bits.
// ===========================================================================
#define BQ 64
#define BKV 64
#define FQ_ST 132
#define FK_ST 132
#define FV_ST 136
#define FS_ST 68

#define OFF_Q  0
#define OFF_K  (OFF_Q + BQ * FQ_ST)
#define OFF_V  (OFF_K + 2 * BKV * FK_ST)
#define OFF_S  (OFF_V + 2 * BKV * FV_ST)
#define OFF_RED (OFF_S + BQ * FS_ST)
#define OFF_M  (OFF_RED + 256)
#define OFF_L  (OFF_M + BQ)
#define OFF_SC (OFF_L + BQ)
#define FLASH_SMEM_FLOATS (OFF_SC + BQ)
#define FLASH_SMEM_BYTES (FLASH_SMEM_FLOATS * 4)

__global__ __launch_bounds__(256) void flash_kernel(
    const float* __restrict__ Q, const float* __restrict__ K,
    const float* __restrict__ V, float* __restrict__ O)
{
    extern __shared__ float sm[];
    uint32_t* smu = (uint32_t*)sm;
    float* Ks = sm + OFF_K;
    float* Vs = sm + OFF_V;
    uint32_t* Qs = smu + OFF_Q;
    uint32_t* Ss = smu + OFF_S;
    float* red = sm + OFF_RED;
    float* m_s = sm + OFF_M;
    float* l_s = sm + OFF_L;
    float* sc_s = sm + OFF_SC;

    const int qt = (int)gridDim.x - 1 - (int)blockIdx.x;   // heavy tiles first
    const int bh = blockIdx.y;
    const int b = bh >> 4;
    const int h = bh & 15;
    const int tid = threadIdx.x;
    const int wid = tid >> 5;
    const int lane = tid & 31;
    const int warp_m = wid >> 1;
    const int warp_n = wid & 1;
    const int lr = lane >> 2;
    const int kc = lane & 3;

    const size_t head_base = (size_t)b * SEQLEN * DIM + (size_t)h * HD;
    const float* Qg = Q + head_base + (size_t)(qt * BQ) * DIM;
    const float scale = 0.08838834764831845f;   // 1/sqrt(128)

#pragma unroll
    for (int i = 0; i < 8; ++i) {
        int e = tid + i * 256;
        int r = e >> 5;
        int c = (e & 31) << 2;
        float4 v4 = *(const float4*)(Qg + (size_t)r * DIM + c);
        Qs[r * FQ_ST + c + 0] = f2tf32(v4.x * scale);
        Qs[r * FQ_ST + c + 1] = f2tf32(v4.y * scale);
        Qs[r * FQ_ST + c + 2] = f2tf32(v4.z * scale);
        Qs[r * FQ_ST + c + 3] = f2tf32(v4.w * scale);
    }
    if (tid < BQ) { m_s[tid] = -1e30f; l_s[tid] = 0.0f; }

    float accO[8][4];
#pragma unroll
    for (int i = 0; i < 8; ++i)
#pragma unroll
        for (int r = 0; r < 4; ++r) accO[i][r] = 0.0f;

    const uint32_t k_su = smem_u32(Ks);
    const uint32_t v_su = smem_u32(Vs);
    auto prefetch = [&](int kt, int buf) {
        const float* Kg = K + head_base + (size_t)(kt * BKV) * DIM;
        const float* Vg = V + head_base + (size_t)(kt * BKV) * DIM;
        const uint32_t kb = k_su + buf * (BKV * FK_ST * 4);
        const uint32_t vb = v_su + buf * (BKV * FV_ST * 4);
#pragma unroll
        for (int i = 0; i < 8; ++i) {
            int e = tid + i * 256;
            int r = e >> 5;
            int c = (e & 31) << 2;
            cp_async16(kb + (r * FK_ST + c) * 4, Kg + (size_t)r * DIM + c);
            cp_async16(vb + (r * FV_ST + c) * 4, Vg + (size_t)r * DIM + c);
        }
        CP_COMMIT();
    };

    prefetch(0, 0);
    __syncthreads();

    const int ntiles = qt + 1;
    for (int kt = 0; kt < ntiles; ++kt) {
        const int buf = kt & 1;
        const bool more = (kt + 1 < ntiles);
        if (more) prefetch(kt + 1, buf ^ 1);
        if (more) { CP_WAIT(1); } else { CP_WAIT(0); }
        __syncthreads();

        // ---- QK^T: 16x32 warp tile ----
        float accS[4][4];
#pragma unroll
        for (int nf = 0; nf < 4; ++nf)
#pragma unroll
            for (int r = 0; r < 4; ++r) accS[nf][r] = 0.0f;

        const uint32_t* Qw = Qs + (warp_m * 16 + lr) * FQ_ST + kc;
        const float* Kw = Ks + (size_t)buf * (BKV * FK_ST) +
                          (warp_n * 32 + lr) * FK_ST + kc;
#pragma unroll
        for (int ks = 0; ks < 16; ++ks) {
            uint32_t a[4];
            const uint32_t* ap = Qw + ks * 8;
            a[0] = ap[0];
            a[1] = ap[8 * FQ_ST];
            a[2] = ap[4];
            a[3] = ap[8 * FQ_ST + 4];
#pragma unroll
            for (int nf = 0; nf < 4; ++nf) {
                const float* bp = Kw + nf * 8 * FK_ST + ks * 8;
                uint32_t bfr[2];
                bfr[0] = f2tf32(bp[0]);
                bfr[1] = f2tf32(bp[4]);
                mma_tf32(accS[nf], a, bfr);
            }
        }

        const bool diag = (kt == qt);
        const int r0 = warp_m * 16 + lr;
#pragma unroll
        for (int nf = 0; nf < 4; ++nf) {
            int cb = warp_n * 32 + nf * 8 + kc * 2;
            float v0 = accS[nf][0], v1 = accS[nf][1];
            float v2 = accS[nf][2], v3 = accS[nf][3];
            if (diag) {
                if (cb > r0)      v0 = -1e30f;
                if (cb + 1 > r0)  v1 = -1e30f;
                if (cb > r0 + 8)     v2 = -1e30f;
                if (cb + 1 > r0 + 8) v3 = -1e30f;
            }
            Ss[r0 * FS_ST + cb]           = __float_as_uint(v0);
            Ss[r0 * FS_ST + cb + 1]       = __float_as_uint(v1);
            Ss[(r0 + 8) * FS_ST + cb]     = __float_as_uint(v2);
            Ss[(r0 + 8) * FS_ST + cb + 1] = __float_as_uint(v3);
        }
        __syncthreads();

        // ---- softmax: 4 threads per row ----
        const int srow = tid & 63;
        const int sq = tid >> 6;
        {
            float mx = -1e30f;
#pragma unroll
            for (int j = 0; j < 16; ++j)
                mx = fmaxf(mx, __uint_as_float(Ss[srow * FS_ST + sq * 16 + j]));
            red[sq * 64 + srow] = mx;
        }
        __syncthreads();
        if (tid < BQ) {
            float mold = m_s[tid];
            float mt = fmaxf(fmaxf(red[tid], red[64 + tid]),
                             fmaxf(red[128 + tid], red[192 + tid]));
            float mnew = fmaxf(mold, mt);
            m_s[tid] = mnew;
            sc_s[tid] = __expf(mold - mnew);
        }
        __syncthreads();
        {
            float mnew = m_s[srow];
            float sum = 0.0f;
#pragma unroll
            for (int j = 0; j < 16; ++j) {
                int idx = srow * FS_ST + sq * 16 + j;
                float e = __expf(__uint_as_float(Ss[idx]) - mnew);
                Ss[idx] = f2tf32(e);
                sum += e;
            }
            red[sq * 64 + srow] = sum;
        }
        __syncthreads();
        if (tid < BQ) {
            l_s[tid] = l_s[tid] * sc_s[tid] +
                       (red[tid] + red[64 + tid] + red[128 + tid] + red[192 + tid]);
        }

        // ---- rescale O, then O += P @ V ----
        const float scr0 = sc_s[r0];
        const float scr1 = sc_s[r0 + 8];
#pragma unroll
        for (int nf = 0; nf < 8; ++nf) {
            accO[nf][0] *= scr0;
            accO[nf][1] *= scr0;
            accO[nf][2] *= scr1;
            accO[nf][3] *= scr1;
        }

        const uint32_t* Pw = Ss + (warp_m * 16 + lr) * FS_ST + kc;
        const float* Vw = Vs + (size_t)buf * (BKV * FV_ST) +
                          kc * FV_ST + warp_n * 64 + lr;
#pragma unroll
        for (int ks = 0; ks < 8; ++ks) {
            uint32_t a[4];
            const uint32_t* ap = Pw + ks * 8;
            a[0] = ap[0];
            a[1] = ap[8 * FS_ST];
            a[2] = ap[4];
            a[3] = ap[8 * FS_ST + 4];
            const float* bp = Vw + ks * 8 * FV_ST;
#pragma unroll
            for (int nf = 0; nf < 8; ++nf) {
                uint32_t bfr[2];
                bfr[0] = f2tf32(bp[nf * 8]);
                bfr[1] = f2tf32(bp[4 * FV_ST + nf * 8]);
                mma_tf32(accO[nf], a, bfr);
            }
        }
        __syncthreads();
    }

    // ---- normalize + write O as tf32-rounded floats (wo GEMM reads bits) ----
    const int row0 = warp_m * 16 + lr;
    const float inv0 = 1.0f / l_s[row0];
    const float inv1 = 1.0f / l_s[row0 + 8];
    uint32_t* Og = (uint32_t*)(O + head_base + (size_t)(qt * BQ) * DIM);
#pragma unroll
    for (int nf = 0; nf < 8; ++nf) {
        int col = warp_n * 64 + nf * 8 + kc * 2;
        *(uint2*)(Og + (size_t)row0 * DIM + col) =
            make_uint2(f2tf32(accO[nf][0] * inv0), f2tf32(accO[nf][1] * inv0));
        *(uint2*)(Og + (size_t)(row0 + 8) * DIM + col) =
            make_uint2(f2tf32(accO[nf][2] * inv1), f2tf32(accO[nf][3] * inv1));
    }
}

// ---------------------------------------------------------------------------
// Launch. Inputs: 0=x, 1=start_pos, 2=freqs_cos, 3=freqs_sin, 4=mask,
// 5=wq, 6=wk, 7=wv, 8=wo. Output: (B, S, DIM) fp32.
// ---------------------------------------------------------------------------
extern "C" void kernel_launch(void* const* d_in, const int* in_sizes, int n_in,
                              void* d_out, int out_size)
{
    const float* x  = (const float*)d_in[0];
    const float* fc = (const float*)d_in[2];
    const float* fs = (const float*)d_in[3];
    const float* wq = (const float*)d_in[5];
    const float* wk = (const float*)d_in[6];
    const float* wv = (const float*)d_in[7];
    const float* wo = (const float*)d_in[8];
    float* out = (float*)d_out;

    float *qp, *kp, *vp, *ap;
    uint32_t *xt, *wqt, *wkt, *wvt, *wot;
    cudaGetSymbolAddress((void**)&qp, g_q);
    cudaGetSymbolAddress((void**)&kp, g_k);
    cudaGetSymbolAddress((void**)&vp, g_v);
    cudaGetSymbolAddress((void**)&ap, g_att);
    cudaGetSymbolAddress((void**)&xt, g_xt);
    cudaGetSymbolAddress((void**)&wqt, g_wqt);
    cudaGetSymbolAddress((void**)&wkt, g_wkt);
    cudaGetSymbolAddress((void**)&wvt, g_wvt);
    cudaGetSymbolAddress((void**)&wot, g_wot);

    // pre-convert inputs to tf32 bits
    const int n4x = (MROWS * DIM) / 4;
    const int n4w = (DIM * DIM) / 4;
    cvt_tf32_kernel<<<(n4x + 255) / 256, 256>>>((const float4*)x, (uint4*)xt, n4x);
    cvt_tf32_kernel<<<(n4w + 255) / 256, 256>>>((const float4*)wq, (uint4*)wqt, n4w);
    cvt_tf32_kernel<<<(n4w + 255) / 256, 256>>>((const float4*)wk, (uint4*)wkt, n4w);
    cvt_tf32_kernel<<<(n4w + 255) / 256, 256>>>((const float4*)wv, (uint4*)wvt, n4w);
    cvt_tf32_kernel<<<(n4w + 255) / 256, 256>>>((const float4*)wo, (uint4*)wot, n4w);

    cudaFuncSetAttribute(gemm_mma_kernel,
                         cudaFuncAttributeMaxDynamicSharedMemorySize, GEMM_SMEM);

    // fused QKV projection + RoPE epilogue
    dim3 gq(DIM / GBN, MROWS / GBM, 3);
    gemm_mma_kernel<<<gq, 256, GEMM_SMEM>>>(xt, wqt, wkt, wvt,
                                            qp, kp, vp, fc, fs, 1);

    // flash attention (writes tf32-rounded att)
    cudaFuncSetAttribute(flash_kernel,
                         cudaFuncAttributeMaxDynamicSharedMemorySize,
                         FLASH_SMEM_BYTES);
    dim3 fg(SEQLEN / BQ, BSZ * NH);
    flash_kernel<<<fg, 256, FLASH_SMEM_BYTES>>>(qp, kp, vp, ap);

    // output projection
    dim3 go(DIM / GBN, MROWS / GBM, 1);
    gemm_mma_kernel<<<go, 256, GEMM_SMEM>>>((const uint32_t*)ap, wot, wot, wot,
                                            out, out, out, fc, fs, 0);
}

// round 9
// speedup vs baseline: 3.8196x; 1.1023x over previous
#include <cuda_runtime.h>
#include <cuda_bf16.h>
#include <cstdint>
#include <math.h>

#define DIM 2048
#define NH 16
#define HD 128
#define BSZ 2
#define SEQLEN 2048
#define MROWS (BSZ * SEQLEN)

// Scratch (static device arrays — allocation-free per harness rules)
__device__ float g_q[(size_t)MROWS * DIM];
__device__ float g_k[(size_t)MROWS * DIM];
__device__ float g_v[(size_t)MROWS * DIM];
__device__ float g_att[(size_t)MROWS * DIM];
__device__ uint32_t g_xt[(size_t)MROWS * DIM];
__device__ uint32_t g_wqt[(size_t)DIM * DIM];
__device__ uint32_t g_wkt[(size_t)DIM * DIM];
__device__ uint32_t g_wvt[(size_t)DIM * DIM];
__device__ uint32_t g_wot[(size_t)DIM * DIM];

__device__ __forceinline__ uint32_t f2tf32(float x) {
    uint32_t r;
    asm("cvt.rna.tf32.f32 %0, %1;" : "=r"(r) : "f"(x));
    return r;
}

__device__ __forceinline__ void mma_tf32(float* c, const uint32_t* a,
                                         const uint32_t* b) {
    asm volatile(
        "mma.sync.aligned.m16n8k8.row.col.f32.tf32.tf32.f32 "
        "{%0,%1,%2,%3}, {%4,%5,%6,%7}, {%8,%9}, {%0,%1,%2,%3};"
        : "+f"(c[0]), "+f"(c[1]), "+f"(c[2]), "+f"(c[3])
        : "r"(a[0]), "r"(a[1]), "r"(a[2]), "r"(a[3]), "r"(b[0]), "r"(b[1]));
}

__device__ __forceinline__ uint32_t smem_u32(const void* p) {
    uint32_t a;
    asm("{ .reg .u64 t; cvta.to.shared.u64 t, %1; cvt.u32.u64 %0, t; }"
        : "=r"(a) : "l"(p));
    return a;
}
__device__ __forceinline__ void cp_async16(uint32_t dst, const void* src) {
    asm volatile("cp.async.cg.shared.global [%0], [%1], 16;"
                 :: "r"(dst), "l"(src) : "memory");
}
#define CP_COMMIT() asm volatile("cp.async.commit_group;" ::: "memory")
#define CP_WAIT(N)  asm volatile("cp.async.wait_group %0;" :: "n"(N) : "memory")

// ---------------------------------------------------------------------------
// fp32 -> tf32-bits elementwise convert (vectorized)
// ---------------------------------------------------------------------------
__global__ __launch_bounds__(256) void cvt_tf32_kernel(
    const float4* __restrict__ in, uint4* __restrict__ out, int n4)
{
    int i = blockIdx.x * blockDim.x + threadIdx.x;
    if (i >= n4) return;
    float4 v = in[i];
    out[i] = make_uint4(f2tf32(v.x), f2tf32(v.y), f2tf32(v.z), f2tf32(v.w));
}

// ===========================================================================
// tf32 mma.sync GEMM on pre-converted tf32 bits. C = A * B^T.
// 128x128x32 block tile, 8 warps, 3-buffer cp.async pipeline, 2 CTAs/SM.
// Prefetch of buffer (s+2)%3 is issued AFTER the stage-s __syncthreads so the
// write is ordered after all stage-(s-1) readers of that buffer (WAR safety).
// grid.z selects (B, C); RoPE fused in epilogue when do_rope && z < 2.
// ===========================================================================
#define GBM 128
#define GBN 128
#define GBK 32
#define GST 36
#define GT_U32 (GBM * GST)
#define GSTAGE_U32 (2 * GT_U32)
#define GNBUF 3
#define GEMM_SMEM (GNBUF * GSTAGE_U32 * 4)   // 110592 bytes
#define NSTAGE (DIM / GBK)                   // 64

__global__ __launch_bounds__(256, 2) void gemm_mma_kernel(
    const uint32_t* __restrict__ A,
    const uint32_t* __restrict__ B0, const uint32_t* __restrict__ B1,
    const uint32_t* __restrict__ B2,
    float* __restrict__ C0, float* __restrict__ C1, float* __restrict__ C2,
    const float* __restrict__ cosf, const float* __restrict__ sinf,
    int do_rope)
{
    extern __shared__ uint32_t smem[];
    const int tid = threadIdx.x;
    const int wid = tid >> 5;
    const int lane = tid & 31;
    const int warp_m = wid >> 2;
    const int warp_n = wid & 3;
    const int bm = blockIdx.y * GBM;
    const int bn = blockIdx.x * GBN;
    const int z = blockIdx.z;

    const uint32_t* B = (z == 0) ? B0 : (z == 1) ? B1 : B2;
    float* C = (z == 0) ? C0 : (z == 1) ? C1 : C2;
    const bool rope = do_rope && (z < 2);

    const uint32_t smem_base = smem_u32(smem);

    float acc[4][4][4];
#pragma unroll
    for (int i = 0; i < 4; ++i)
#pragma unroll
        for (int j = 0; j < 4; ++j)
#pragma unroll
            for (int r = 0; r < 4; ++r) acc[i][j][r] = 0.0f;

    const int pr = tid >> 3;
    const int pc = tid & 7;
    auto prefetch = [&](int s) {
        const int k0 = s * GBK;
        const uint32_t sb = smem_base + (s % GNBUF) * (GSTAGE_U32 * 4);
#pragma unroll
        for (int i = 0; i < 4; ++i) {
            int r = pr + i * 32;
            cp_async16(sb + (r * GST + pc * 4) * 4,
                       A + (size_t)(bm + r) * DIM + k0 + pc * 4);
            cp_async16(sb + (GT_U32 + r * GST + pc * 4) * 4,
                       B + (size_t)(bn + r) * DIM + k0 + pc * 4);
        }
        CP_COMMIT();
    };

    prefetch(0);
    prefetch(1);

    const int arow = warp_m * 64 + (lane >> 2);
    const int brow = warp_n * 32 + (lane >> 2);
    const int kc = lane & 3;

    for (int s = 0; s < NSTAGE; ++s) {
        if (s + 1 < NSTAGE) { CP_WAIT(1); } else { CP_WAIT(0); }
        __syncthreads();
        if (s + 2 < NSTAGE) prefetch(s + 2);   // after sync: WAR-safe

        const uint32_t* Asm = smem + (s % GNBUF) * GSTAGE_U32;
        const uint32_t* Bsm = Asm + GT_U32;

#pragma unroll
        for (int ks = 0; ks < 4; ++ks) {
            uint32_t af[4][4];
#pragma unroll
            for (int mt = 0; mt < 4; ++mt) {
                const uint32_t* p = Asm + (arow + mt * 16) * GST + ks * 8 + kc;
                af[mt][0] = p[0];
                af[mt][1] = p[8 * GST];
                af[mt][2] = p[4];
                af[mt][3] = p[8 * GST + 4];
            }
            uint32_t bf[4][2];
#pragma unroll
            for (int nt = 0; nt < 4; ++nt) {
                const uint32_t* p = Bsm + (brow + nt * 8) * GST + ks * 8 + kc;
                bf[nt][0] = p[0];
                bf[nt][1] = p[4];
            }
#pragma unroll
            for (int mt = 0; mt < 4; ++mt)
#pragma unroll
                for (int nt = 0; nt < 4; ++nt)
                    mma_tf32(acc[mt][nt], af[mt], bf[nt]);
        }
    }

    // epilogue (optionally fused RoPE: each float2 is one rope pair)
#pragma unroll
    for (int mt = 0; mt < 4; ++mt) {
        const int row0 = bm + warp_m * 64 + mt * 16 + (lane >> 2);
        const int s0 = row0 & (SEQLEN - 1);
#pragma unroll
        for (int nt = 0; nt < 4; ++nt) {
            const int col = bn + warp_n * 32 + nt * 8 + (lane & 3) * 2;
            float v0 = acc[mt][nt][0], v1 = acc[mt][nt][1];
            float v2 = acc[mt][nt][2], v3 = acc[mt][nt][3];
            if (rope) {
                const int p = (col & (HD - 1)) >> 1;
                float c0 = cosf[s0 * 64 + p], n0 = sinf[s0 * 64 + p];
                float c1 = cosf[(s0 + 8) * 64 + p], n1 = sinf[(s0 + 8) * 64 + p];
                float t0 = v0 * c0 - v1 * n0;
                v1 = v0 * n0 + v1 * c0; v0 = t0;
                float t2 = v2 * c1 - v3 * n1;
                v3 = v2 * n1 + v3 * c1; v2 = t2;
            }
            *(float2*)(C + (size_t)row0 * DIM + col) = make_float2(v0, v1);
            *(float2*)(C + (size_t)(row0 + 8) * DIM + col) = make_float2(v2, v3);
        }
    }
}

// ===========================================================================
// Flash attention, tf32 mma.sync. BQ=64, BKV=32, 256 threads, 2 CTAs/SM.
// QK^T: warp tile 16x16 (4x2 warps). PV: warp tile 16x64.
// K/V double-buffered via cp.async (loop-end sync orders WAR).
// ===========================================================================
#define BQ 64
#define BKV 32
#define FQ_ST 132
#define FK_ST 132
#define FV_ST 136
#define FS_ST 36

#define OFF_Q  0
#define OFF_K  (OFF_Q + BQ * FQ_ST)
#define OFF_V  (OFF_K + 2 * BKV * FK_ST)
#define OFF_S  (OFF_V + 2 * BKV * FV_ST)
#define OFF_RED (OFF_S + BQ * FS_ST)
#define OFF_M  (OFF_RED + 256)
#define OFF_L  (OFF_M + BQ)
#define OFF_SC (OFF_L + BQ)
#define FLASH_SMEM_FLOATS (OFF_SC + BQ)
#define FLASH_SMEM_BYTES (FLASH_SMEM_FLOATS * 4)    // ~113KB

__global__ __launch_bounds__(256, 2) void flash_kernel(
    const float* __restrict__ Q, const float* __restrict__ K,
    const float* __restrict__ V, float* __restrict__ O)
{
    extern __shared__ float sm[];
    uint32_t* smu = (uint32_t*)sm;
    float* Ks = sm + OFF_K;
    float* Vs = sm + OFF_V;
    uint32_t* Qs = smu + OFF_Q;
    uint32_t* Ss = smu + OFF_S;
    float* red = sm + OFF_RED;
    float* m_s = sm + OFF_M;
    float* l_s = sm + OFF_L;
    float* sc_s = sm + OFF_SC;

    const int qt = (int)gridDim.x - 1 - (int)blockIdx.x;   // heavy tiles first
    const int bh = blockIdx.y;
    const int b = bh >> 4;
    const int h = bh & 15;
    const int tid = threadIdx.x;
    const int wid = tid >> 5;
    const int lane = tid & 31;
    const int warp_m = wid >> 1;     // 0..3
    const int warp_n = wid & 1;      // 0..1
    const int lr = lane >> 2;        // 0..7
    const int kc = lane & 3;         // 0..3

    const size_t head_base = (size_t)b * SEQLEN * DIM + (size_t)h * HD;
    const float* Qg = Q + head_base + (size_t)(qt * BQ) * DIM;
    const float scale = 0.08838834764831845f;   // 1/sqrt(128)

    // Load Q (scale folded, converted to tf32 once)
#pragma unroll
    for (int i = 0; i < 8; ++i) {
        int e = tid + i * 256;
        int r = e >> 5;
        int c = (e & 31) << 2;
        float4 v4 = *(const float4*)(Qg + (size_t)r * DIM + c);
        Qs[r * FQ_ST + c + 0] = f2tf32(v4.x * scale);
        Qs[r * FQ_ST + c + 1] = f2tf32(v4.y * scale);
        Qs[r * FQ_ST + c + 2] = f2tf32(v4.z * scale);
        Qs[r * FQ_ST + c + 3] = f2tf32(v4.w * scale);
    }
    if (tid < BQ) { m_s[tid] = -1e30f; l_s[tid] = 0.0f; }

    float accO[8][4];
#pragma unroll
    for (int i = 0; i < 8; ++i)
#pragma unroll
        for (int r = 0; r < 4; ++r) accO[i][r] = 0.0f;

    const uint32_t k_su = smem_u32(Ks);
    const uint32_t v_su = smem_u32(Vs);
    auto prefetch = [&](int kt, int buf) {
        const float* Kg = K + head_base + (size_t)(kt * BKV) * DIM;
        const float* Vg = V + head_base + (size_t)(kt * BKV) * DIM;
        const uint32_t kb = k_su + buf * (BKV * FK_ST * 4);
        const uint32_t vb = v_su + buf * (BKV * FV_ST * 4);
#pragma unroll
        for (int i = 0; i < 4; ++i) {
            int e = tid + i * 256;       // 0..1023
            int r = e >> 5;              // 0..31
            int c = (e & 31) << 2;       // 0..124
            cp_async16(kb + (r * FK_ST + c) * 4, Kg + (size_t)r * DIM + c);
            cp_async16(vb + (r * FV_ST + c) * 4, Vg + (size_t)r * DIM + c);
        }
        CP_COMMIT();
    };

    prefetch(0, 0);
    __syncthreads();   // Q visible (and m/l init)

    const int ntiles = 2 * (qt + 1);
    for (int kt = 0; kt < ntiles; ++kt) {
        const int buf = kt & 1;
        const bool more = (kt + 1 < ntiles);
        if (more) prefetch(kt + 1, buf ^ 1);
        if (more) { CP_WAIT(1); } else { CP_WAIT(0); }
        __syncthreads();

        // ---- QK^T: 16x16 warp tile (nf = 2) ----
        float accS[2][4];
#pragma unroll
        for (int nf = 0; nf < 2; ++nf)
#pragma unroll
            for (int r = 0; r < 4; ++r) accS[nf][r] = 0.0f;

        const uint32_t* Qw = Qs + (warp_m * 16 + lr) * FQ_ST + kc;
        const float* Kw = Ks + (size_t)buf * (BKV * FK_ST) +
                          (warp_n * 16 + lr) * FK_ST + kc;
#pragma unroll
        for (int ks = 0; ks < 16; ++ks) {
            uint32_t a[4];
            const uint32_t* ap = Qw + ks * 8;
            a[0] = ap[0];
            a[1] = ap[8 * FQ_ST];
            a[2] = ap[4];
            a[3] = ap[8 * FQ_ST + 4];
#pragma unroll
            for (int nf = 0; nf < 2; ++nf) {
                const float* bp = Kw + nf * 8 * FK_ST + ks * 8;
                uint32_t bfr[2];
                bfr[0] = f2tf32(bp[0]);
                bfr[1] = f2tf32(bp[4]);
                mma_tf32(accS[nf], a, bfr);
            }
        }

        // ---- store scores (absolute causal mask; diag tiles kt >= 2*qt) ----
        const bool diag = (kt >= 2 * qt);
        const int r0 = warp_m * 16 + lr;
        const int rowa0 = qt * BQ + r0;
#pragma unroll
        for (int nf = 0; nf < 2; ++nf) {
            int cb = warp_n * 16 + nf * 8 + kc * 2;
            int ca = kt * BKV + cb;
            float v0 = accS[nf][0], v1 = accS[nf][1];
            float v2 = accS[nf][2], v3 = accS[nf][3];
            if (diag) {
                if (ca > rowa0)          v0 = -1e30f;
                if (ca + 1 > rowa0)      v1 = -1e30f;
                if (ca > rowa0 + 8)      v2 = -1e30f;
                if (ca + 1 > rowa0 + 8)  v3 = -1e30f;
            }
            Ss[r0 * FS_ST + cb]           = __float_as_uint(v0);
            Ss[r0 * FS_ST + cb + 1]       = __float_as_uint(v1);
            Ss[(r0 + 8) * FS_ST + cb]     = __float_as_uint(v2);
            Ss[(r0 + 8) * FS_ST + cb + 1] = __float_as_uint(v3);
        }
        __syncthreads();

        // ---- softmax: 4 threads per row, 8 cols each ----
        const int srow = tid & 63;
        const int sq = tid >> 6;
        {
            float mx = -1e30f;
#pragma unroll
            for (int j = 0; j < 8; ++j)
                mx = fmaxf(mx, __uint_as_float(Ss[srow * FS_ST + sq * 8 + j]));
            red[sq * 64 + srow] = mx;
        }
        __syncthreads();
        if (tid < BQ) {
            float mold = m_s[tid];
            float mt = fmaxf(fmaxf(red[tid], red[64 + tid]),
                             fmaxf(red[128 + tid], red[192 + tid]));
            float mnew = fmaxf(mold, mt);
            m_s[tid] = mnew;
            sc_s[tid] = __expf(mold - mnew);
        }
        __syncthreads();
        {
            float mnew = m_s[srow];
            float sum = 0.0f;
#pragma unroll
            for (int j = 0; j < 8; ++j) {
                int idx = srow * FS_ST + sq * 8 + j;
                float e = __expf(__uint_as_float(Ss[idx]) - mnew);
                Ss[idx] = f2tf32(e);
                sum += e;
            }
            red[sq * 64 + srow] = sum;
        }
        __syncthreads();
        if (tid < BQ) {
            l_s[tid] = l_s[tid] * sc_s[tid] +
                       (red[tid] + red[64 + tid] + red[128 + tid] + red[192 + tid]);
        }

        // ---- rescale O, then O += P @ V (16x64 warp tile, K=32) ----
        const float scr0 = sc_s[r0];
        const float scr1 = sc_s[r0 + 8];
#pragma unroll
        for (int nf = 0; nf < 8; ++nf) {
            accO[nf][0] *= scr0;
            accO[nf][1] *= scr0;
            accO[nf][2] *= scr1;
            accO[nf][3] *= scr1;
        }

        const uint32_t* Pw = Ss + (warp_m * 16 + lr) * FS_ST + kc;
        const float* Vw = Vs + (size_t)buf * (BKV * FV_ST) +
                          kc * FV_ST + warp_n * 64 + lr;
#pragma unroll
        for (int ks = 0; ks < 4; ++ks) {
            uint32_t a[4];
            const uint32_t* ap = Pw + ks * 8;
            a[0] = ap[0];
            a[1] = ap[8 * FS_ST];
            a[2] = ap[4];
            a[3] = ap[8 * FS_ST + 4];
            const float* bp = Vw + ks * 8 * FV_ST;
#pragma unroll
            for (int nf = 0; nf < 8; ++nf) {
                uint32_t bfr[2];
                bfr[0] = f2tf32(bp[nf * 8]);
                bfr[1] = f2tf32(bp[4 * FV_ST + nf * 8]);
                mma_tf32(accO[nf], a, bfr);
            }
        }
        __syncthreads();
    }

    // ---- normalize + write O as tf32-rounded floats (wo GEMM reads bits) ----
    const int row0 = warp_m * 16 + lr;
    const float inv0 = 1.0f / l_s[row0];
    const float inv1 = 1.0f / l_s[row0 + 8];
    uint32_t* Og = (uint32_t*)(O + head_base + (size_t)(qt * BQ) * DIM);
#pragma unroll
    for (int nf = 0; nf < 8; ++nf) {
        int col = warp_n * 64 + nf * 8 + kc * 2;
        *(uint2*)(Og + (size_t)row0 * DIM + col) =
            make_uint2(f2tf32(accO[nf][0] * inv0), f2tf32(accO[nf][1] * inv0));
        *(uint2*)(Og + (size_t)(row0 + 8) * DIM + col) =
            make_uint2(f2tf32(accO[nf][2] * inv1), f2tf32(accO[nf][3] * inv1));
    }
}

// ---------------------------------------------------------------------------
// Launch. Inputs: 0=x, 1=start_pos, 2=freqs_cos, 3=freqs_sin, 4=mask,
// 5=wq, 6=wk, 7=wv, 8=wo. Output: (B, S, DIM) fp32.
// ---------------------------------------------------------------------------
extern "C" void kernel_launch(void* const* d_in, const int* in_sizes, int n_in,
                              void* d_out, int out_size)
{
    const float* x  = (const float*)d_in[0];
    const float* fc = (const float*)d_in[2];
    const float* fs = (const float*)d_in[3];
    const float* wq = (const float*)d_in[5];
    const float* wk = (const float*)d_in[6];
    const float* wv = (const float*)d_in[7];
    const float* wo = (const float*)d_in[8];
    float* out = (float*)d_out;

    float *qp, *kp, *vp, *ap;
    uint32_t *xt, *wqt, *wkt, *wvt, *wot;
    cudaGetSymbolAddress((void**)&qp, g_q);
    cudaGetSymbolAddress((void**)&kp, g_k);
    cudaGetSymbolAddress((void**)&vp, g_v);
    cudaGetSymbolAddress((void**)&ap, g_att);
    cudaGetSymbolAddress((void**)&xt, g_xt);
    cudaGetSymbolAddress((void**)&wqt, g_wqt);
    cudaGetSymbolAddress((void**)&wkt, g_wkt);
    cudaGetSymbolAddress((void**)&wvt, g_wvt);
    cudaGetSymbolAddress((void**)&wot, g_wot);

    // pre-convert inputs to tf32 bits
    const int n4x = (MROWS * DIM) / 4;
    const int n4w = (DIM * DIM) / 4;
    cvt_tf32_kernel<<<(n4x + 255) / 256, 256>>>((const float4*)x, (uint4*)xt, n4x);
    cvt_tf32_kernel<<<(n4w + 255) / 256, 256>>>((const float4*)wq, (uint4*)wqt, n4w);
    cvt_tf32_kernel<<<(n4w + 255) / 256, 256>>>((const float4*)wk, (uint4*)wkt, n4w);
    cvt_tf32_kernel<<<(n4w + 255) / 256, 256>>>((const float4*)wv, (uint4*)wvt, n4w);
    cvt_tf32_kernel<<<(n4w + 255) / 256, 256>>>((const float4*)wo, (uint4*)wot, n4w);

    cudaFuncSetAttribute(gemm_mma_kernel,
                         cudaFuncAttributeMaxDynamicSharedMemorySize, GEMM_SMEM);

    // fused QKV projection + RoPE epilogue
    dim3 gq(DIM / GBN, MROWS / GBM, 3);
    gemm_mma_kernel<<<gq, 256, GEMM_SMEM>>>(xt, wqt, wkt, wvt,
                                            qp, kp, vp, fc, fs, 1);

    // flash attention (writes tf32-rounded att)
    cudaFuncSetAttribute(flash_kernel,
                         cudaFuncAttributeMaxDynamicSharedMemorySize,
                         FLASH_SMEM_BYTES);
    dim3 fg(SEQLEN / BQ, BSZ * NH);
    flash_kernel<<<fg, 256, FLASH_SMEM_BYTES>>>(qp, kp, vp, ap);

    // output projection
    dim3 go(DIM / GBN, MROWS / GBM, 1);
    gemm_mma_kernel<<<go, 256, GEMM_SMEM>>>((const uint32_t*)ap, wot, wot, wot,
                                            out, out, out, fc, fs, 0);
}

// round 10
// speedup vs baseline: 6.4087x; 1.6778x over previous
#include <cuda_runtime.h>
#include <cuda_fp16.h>
#include <cstdint>
#include <math.h>

#define DIM 2048
#define NH 16
#define HD 128
#define BSZ 2
#define SEQLEN 2048
#define MROWS (BSZ * SEQLEN)

// Scratch (static device arrays — allocation-free per harness rules)
__device__ __half g_q[(size_t)MROWS * DIM];
__device__ __half g_k[(size_t)MROWS * DIM];
__device__ __half g_v[(size_t)MROWS * DIM];
__device__ __half g_att[(size_t)MROWS * DIM];
__device__ __half g_xh[(size_t)MROWS * DIM];
__device__ __half g_wqh[(size_t)DIM * DIM];
__device__ __half g_wkh[(size_t)DIM * DIM];
__device__ __half g_wvh[(size_t)DIM * DIM];
__device__ __half g_woh[(size_t)DIM * DIM];

__device__ __forceinline__ void mma_f16(float* c, const uint32_t* a,
                                        const uint32_t* b) {
    asm volatile(
        "mma.sync.aligned.m16n8k16.row.col.f32.f16.f16.f32 "
        "{%0,%1,%2,%3}, {%4,%5,%6,%7}, {%8,%9}, {%0,%1,%2,%3};"
        : "+f"(c[0]), "+f"(c[1]), "+f"(c[2]), "+f"(c[3])
        : "r"(a[0]), "r"(a[1]), "r"(a[2]), "r"(a[3]), "r"(b[0]), "r"(b[1]));
}

__device__ __forceinline__ void ldmatrix_x2_trans(uint32_t& r0, uint32_t& r1,
                                                  uint32_t addr) {
    asm volatile("ldmatrix.sync.aligned.m8n8.x2.trans.shared.b16 {%0,%1}, [%2];"
                 : "=r"(r0), "=r"(r1) : "r"(addr));
}

__device__ __forceinline__ uint32_t smem_u32(const void* p) {
    uint32_t a;
    asm("{ .reg .u64 t; cvta.to.shared.u64 t, %1; cvt.u32.u64 %0, t; }"
        : "=r"(a) : "l"(p));
    return a;
}
__device__ __forceinline__ void cp_async16(uint32_t dst, const void* src) {
    asm volatile("cp.async.cg.shared.global [%0], [%1], 16;"
                 :: "r"(dst), "l"(src) : "memory");
}
#define CP_COMMIT() asm volatile("cp.async.commit_group;" ::: "memory")
#define CP_WAIT(N)  asm volatile("cp.async.wait_group %0;" :: "n"(N) : "memory")

// ---------------------------------------------------------------------------
// fp32 -> fp16 elementwise convert (vectorized)
// ---------------------------------------------------------------------------
__global__ __launch_bounds__(256) void cvt_f16_kernel(
    const float4* __restrict__ in, uint2* __restrict__ out, int n4)
{
    int i = blockIdx.x * blockDim.x + threadIdx.x;
    if (i >= n4) return;
    float4 v = in[i];
    __half2 h0 = __floats2half2_rn(v.x, v.y);
    __half2 h1 = __floats2half2_rn(v.z, v.w);
    uint2 u;
    u.x = *(uint32_t*)&h0;
    u.y = *(uint32_t*)&h1;
    out[i] = u;
}

// ===========================================================================
// fp16 mma.sync GEMM: C = A * B^T. A [M][K], B [N][K] fp16.
// 128x128x32 block tile, 8 warps (2x4), warp tile 64x32, m16n8k16,
// 3-buffer cp.async pipeline, 2 CTAs/SM.
// qkv_mode: outputs fp16 with RoPE (z<2) and q-scale (z==0); else fp32 out.
// ===========================================================================
#define GBM 128
#define GBN 128
#define GBK 32
#define GSTH 40                 // halfs per smem row (20 words: conflict-free)
#define GSTW 20
#define GT_H (GBM * GSTH)       // 5120 halfs
#define GT_W (GT_H / 2)         // 2560 words
#define GSTAGE_H (2 * GT_H)
#define GSTAGE_W (2 * GT_W)
#define GNBUF 3
#define GEMM_SMEM (GNBUF * GSTAGE_H * 2)   // 61440 bytes
#define NSTAGE (DIM / GBK)                 // 64

__global__ __launch_bounds__(256, 2) void gemm_f16_kernel(
    const __half* __restrict__ A,
    const __half* __restrict__ B0, const __half* __restrict__ B1,
    const __half* __restrict__ B2,
    void* C0, void* C1, void* C2,
    const float* __restrict__ cosf, const float* __restrict__ sinf,
    int qkv_mode)
{
    extern __shared__ __half smh[];
    const int tid = threadIdx.x;
    const int wid = tid >> 5;
    const int lane = tid & 31;
    const int warp_m = wid >> 2;
    const int warp_n = wid & 3;
    const int bm = blockIdx.y * GBM;
    const int bn = blockIdx.x * GBN;
    const int z = blockIdx.z;

    const __half* B = (z == 0) ? B0 : (z == 1) ? B1 : B2;
    void* C = (z == 0) ? C0 : (z == 1) ? C1 : C2;

    const uint32_t smem_base = smem_u32(smh);

    float acc[4][4][4];
#pragma unroll
    for (int i = 0; i < 4; ++i)
#pragma unroll
        for (int j = 0; j < 4; ++j)
#pragma unroll
            for (int r = 0; r < 4; ++r) acc[i][j][r] = 0.0f;

    // per-stage: A,B tiles 128 rows x 32 halfs; 4 x 16B chunks per row
    const int pr4 = tid >> 2;      // 0..63
    const int pc4 = tid & 3;       // 0..3
    auto prefetch = [&](int s) {
        const int k0 = s * GBK;
        const uint32_t sb = smem_base + (s % GNBUF) * (GSTAGE_H * 2);
#pragma unroll
        for (int i = 0; i < 2; ++i) {
            int r = pr4 + i * 64;
            cp_async16(sb + (r * GSTH + pc4 * 8) * 2,
                       A + (size_t)(bm + r) * DIM + k0 + pc4 * 8);
            cp_async16(sb + (GT_H + r * GSTH + pc4 * 8) * 2,
                       B + (size_t)(bn + r) * DIM + k0 + pc4 * 8);
        }
        CP_COMMIT();
    };

    prefetch(0);
    prefetch(1);

    const int arow = warp_m * 64 + (lane >> 2);
    const int brow = warp_n * 32 + (lane >> 2);
    const int kc = lane & 3;

    for (int s = 0; s < NSTAGE; ++s) {
        if (s + 1 < NSTAGE) { CP_WAIT(1); } else { CP_WAIT(0); }
        __syncthreads();
        if (s + 2 < NSTAGE) prefetch(s + 2);   // after sync: WAR-safe

        const uint32_t* Asm = (const uint32_t*)smh + (s % GNBUF) * GSTAGE_W;
        const uint32_t* Bsm = Asm + GT_W;

#pragma unroll
        for (int ks = 0; ks < 2; ++ks) {
            uint32_t af[4][4];
#pragma unroll
            for (int mt = 0; mt < 4; ++mt) {
                const uint32_t* p = Asm + (arow + mt * 16) * GSTW + ks * 8 + kc;
                af[mt][0] = p[0];
                af[mt][1] = p[8 * GSTW];
                af[mt][2] = p[4];
                af[mt][3] = p[8 * GSTW + 4];
            }
            uint32_t bf[4][2];
#pragma unroll
            for (int nt = 0; nt < 4; ++nt) {
                const uint32_t* p = Bsm + (brow + nt * 8) * GSTW + ks * 8 + kc;
                bf[nt][0] = p[0];
                bf[nt][1] = p[4];
            }
#pragma unroll
            for (int mt = 0; mt < 4; ++mt)
#pragma unroll
                for (int nt = 0; nt < 4; ++nt)
                    mma_f16(acc[mt][nt], af[mt], bf[nt]);
        }
    }

    // epilogue
    const float qs = (qkv_mode && z == 0) ? 0.08838834764831845f : 1.0f;
#pragma unroll
    for (int mt = 0; mt < 4; ++mt) {
        const int row0 = bm + warp_m * 64 + mt * 16 + (lane >> 2);
        const int s0 = row0 & (SEQLEN - 1);
#pragma unroll
        for (int nt = 0; nt < 4; ++nt) {
            const int col = bn + warp_n * 32 + nt * 8 + (lane & 3) * 2;
            float v0 = acc[mt][nt][0], v1 = acc[mt][nt][1];
            float v2 = acc[mt][nt][2], v3 = acc[mt][nt][3];
            if (qkv_mode) {
                if (z < 2) {   // RoPE for q, k
                    const int p = (col & (HD - 1)) >> 1;
                    float c0 = cosf[s0 * 64 + p], n0 = sinf[s0 * 64 + p];
                    float c1 = cosf[(s0 + 8) * 64 + p], n1 = sinf[(s0 + 8) * 64 + p];
                    float t0 = v0 * c0 - v1 * n0;
                    v1 = v0 * n0 + v1 * c0; v0 = t0;
                    float t2 = v2 * c1 - v3 * n1;
                    v3 = v2 * n1 + v3 * c1; v2 = t2;
                }
                __half* Ch = (__half*)C;
                *(__half2*)(Ch + (size_t)row0 * DIM + col) =
                    __floats2half2_rn(v0 * qs, v1 * qs);
                *(__half2*)(Ch + (size_t)(row0 + 8) * DIM + col) =
                    __floats2half2_rn(v2 * qs, v3 * qs);
            } else {
                float* Cf = (float*)C;
                *(float2*)(Cf + (size_t)row0 * DIM + col) = make_float2(v0, v1);
                *(float2*)(Cf + (size_t)(row0 + 8) * DIM + col) = make_float2(v2, v3);
            }
        }
    }
}

// ===========================================================================
// Flash attention, fp16 mma.sync. BQ=64, BKV=32, 256 threads, 2 CTAs/SM.
// Q pre-scaled by 1/sqrt(hd) in projection. QK^T: warp tile 16x16.
// PV: warp tile 16x64 with V B-fragments via ldmatrix.x2.trans.
// ===========================================================================
#define BQ 64
#define BKV 32
#define FSTH 136          // Q/K/V smem stride in halfs (68 words: 4 mod 32)
#define FSTW 68
#define FS_ST 36          // S stride (floats)
#define FP_STH 40         // P stride (halfs)
#define FP_STW 20

#define Q_BYTES (BQ * FSTH * 2)           // 17408
#define KV_TILE_BYTES (BKV * FSTH * 2)    // 8704
#define OFFB_Q 0
#define OFFB_K (OFFB_Q + Q_BYTES)                 // 17408
#define OFFB_V (OFFB_K + 2 * KV_TILE_BYTES)       // 34816
#define OFFB_S (OFFB_V + 2 * KV_TILE_BYTES)       // 52224
#define OFFB_P (OFFB_S + BQ * FS_ST * 4)          // 61440
#define OFFB_RED (OFFB_P + BQ * FP_STH * 2)       // 66560
#define OFFB_M (OFFB_RED + 256 * 4)
#define OFFB_L (OFFB_M + BQ * 4)
#define OFFB_SC (OFFB_L + BQ * 4)
#define FLASH_SMEM_BYTES (OFFB_SC + BQ * 4)       // 68352

__global__ __launch_bounds__(256, 2) void flash_kernel(
    const __half* __restrict__ Q, const __half* __restrict__ K,
    const __half* __restrict__ V, __half* __restrict__ O)
{
    extern __shared__ char smc[];
    __half* Qs = (__half*)(smc + OFFB_Q);
    __half* Ks = (__half*)(smc + OFFB_K);
    __half* Ps = (__half*)(smc + OFFB_P);
    float* Ss = (float*)(smc + OFFB_S);
    float* red = (float*)(smc + OFFB_RED);
    float* m_s = (float*)(smc + OFFB_M);
    float* l_s = (float*)(smc + OFFB_L);
    float* sc_s = (float*)(smc + OFFB_SC);

    const int qt = (int)gridDim.x - 1 - (int)blockIdx.x;   // heavy tiles first
    const int bh = blockIdx.y;
    const int b = bh >> 4;
    const int h = bh & 15;
    const int tid = threadIdx.x;
    const int wid = tid >> 5;
    const int lane = tid & 31;
    const int warp_m = wid >> 1;     // 0..3
    const int warp_n = wid & 1;      // 0..1
    const int lr = lane >> 2;        // 0..7
    const int kc = lane & 3;         // 0..3

    const size_t head_base = (size_t)b * SEQLEN * DIM + (size_t)h * HD;
    const uint32_t q_su = smem_u32(Qs);
    const uint32_t k_su = smem_u32(Ks);
    const uint32_t v_su = smem_u32(smc + OFFB_V);

    // Load Q tile via cp.async (fp16, already scaled)
    {
        const __half* Qg = Q + head_base + (size_t)(qt * BQ) * DIM;
#pragma unroll
        for (int i = 0; i < 4; ++i) {
            int e = tid + i * 256;        // 0..1023
            int r = e >> 4;               // 0..63
            int c = e & 15;               // 16B chunk (8 halfs)
            cp_async16(q_su + (r * FSTH + c * 8) * 2,
                       Qg + (size_t)r * DIM + c * 8);
        }
        CP_COMMIT();
    }
    if (tid < BQ) { m_s[tid] = -1e30f; l_s[tid] = 0.0f; }

    float accO[8][4];
#pragma unroll
    for (int i = 0; i < 8; ++i)
#pragma unroll
        for (int r = 0; r < 4; ++r) accO[i][r] = 0.0f;

    auto prefetch = [&](int kt, int buf) {
        const __half* Kg = K + head_base + (size_t)(kt * BKV) * DIM;
        const __half* Vg = V + head_base + (size_t)(kt * BKV) * DIM;
        const uint32_t kb = k_su + buf * KV_TILE_BYTES;
        const uint32_t vb = v_su + buf * KV_TILE_BYTES;
#pragma unroll
        for (int i = 0; i < 2; ++i) {
            int e = tid + i * 256;        // 0..511
            int r = e >> 4;               // 0..31
            int c = e & 15;
            cp_async16(kb + (r * FSTH + c * 8) * 2, Kg + (size_t)r * DIM + c * 8);
            cp_async16(vb + (r * FSTH + c * 8) * 2, Vg + (size_t)r * DIM + c * 8);
        }
        CP_COMMIT();
    };

    prefetch(0, 0);
    __syncthreads();

    const int ntiles = 2 * (qt + 1);
    for (int kt = 0; kt < ntiles; ++kt) {
        const int buf = kt & 1;
        const bool more = (kt + 1 < ntiles);
        if (more) prefetch(kt + 1, buf ^ 1);
        if (more) { CP_WAIT(1); } else { CP_WAIT(0); }
        __syncthreads();

        // ---- QK^T: 16x16 warp tile, m16n8k16, ks = HD/16 = 8 ----
        float accS[2][4];
#pragma unroll
        for (int nt = 0; nt < 2; ++nt)
#pragma unroll
            for (int r = 0; r < 4; ++r) accS[nt][r] = 0.0f;

        const uint32_t* Qw = (const uint32_t*)Qs + (warp_m * 16 + lr) * FSTW + kc;
        const uint32_t* Kw = (const uint32_t*)Ks + (size_t)buf * (KV_TILE_BYTES / 4) +
                             (warp_n * 16 + (lane >> 2)) * FSTW + kc;
#pragma unroll
        for (int ks = 0; ks < 8; ++ks) {
            uint32_t a[4];
            const uint32_t* ap = Qw + ks * 8;
            a[0] = ap[0];
            a[1] = ap[8 * FSTW];
            a[2] = ap[4];
            a[3] = ap[8 * FSTW + 4];
#pragma unroll
            for (int nt = 0; nt < 2; ++nt) {
                const uint32_t* bp = Kw + nt * 8 * FSTW + ks * 8;
                uint32_t bfr[2];
                bfr[0] = bp[0];
                bfr[1] = bp[4];
                mma_f16(accS[nt], a, bfr);
            }
        }

        // ---- store scores fp32 (absolute causal mask; kt >= 2*qt) ----
        const bool diag = (kt >= 2 * qt);
        const int r0 = warp_m * 16 + lr;
        const int rowa0 = qt * BQ + r0;
#pragma unroll
        for (int nt = 0; nt < 2; ++nt) {
            int cb = warp_n * 16 + nt * 8 + kc * 2;
            int ca = kt * BKV + cb;
            float v0 = accS[nt][0], v1 = accS[nt][1];
            float v2 = accS[nt][2], v3 = accS[nt][3];
            if (diag) {
                if (ca > rowa0)          v0 = -1e30f;
                if (ca + 1 > rowa0)      v1 = -1e30f;
                if (ca > rowa0 + 8)      v2 = -1e30f;
                if (ca + 1 > rowa0 + 8)  v3 = -1e30f;
            }
            Ss[r0 * FS_ST + cb]           = v0;
            Ss[r0 * FS_ST + cb + 1]       = v1;
            Ss[(r0 + 8) * FS_ST + cb]     = v2;
            Ss[(r0 + 8) * FS_ST + cb + 1] = v3;
        }
        __syncthreads();

        // ---- softmax: 4 threads per row, 8 cols each; P written as half2 ----
        const int srow = tid & 63;
        const int sq = tid >> 6;
        {
            float mx = -1e30f;
#pragma unroll
            for (int j = 0; j < 8; ++j)
                mx = fmaxf(mx, Ss[srow * FS_ST + sq * 8 + j]);
            red[sq * 64 + srow] = mx;
        }
        __syncthreads();
        if (tid < BQ) {
            float mold = m_s[tid];
            float mt = fmaxf(fmaxf(red[tid], red[64 + tid]),
                             fmaxf(red[128 + tid], red[192 + tid]));
            float mnew = fmaxf(mold, mt);
            m_s[tid] = mnew;
            sc_s[tid] = __expf(mold - mnew);
        }
        __syncthreads();
        {
            float mnew = m_s[srow];
            float e8[8];
            float sum = 0.0f;
#pragma unroll
            for (int j = 0; j < 8; ++j) {
                e8[j] = __expf(Ss[srow * FS_ST + sq * 8 + j] - mnew);
                sum += e8[j];
            }
#pragma unroll
            for (int j = 0; j < 8; j += 2)
                *(__half2*)(Ps + srow * FP_STH + sq * 8 + j) =
                    __floats2half2_rn(e8[j], e8[j + 1]);
            red[sq * 64 + srow] = sum;
        }
        __syncthreads();
        if (tid < BQ) {
            l_s[tid] = l_s[tid] * sc_s[tid] +
                       (red[tid] + red[64 + tid] + red[128 + tid] + red[192 + tid]);
        }

        // ---- rescale O, then O += P @ V (16x64 warp tile, K=32, ks=2) ----
        const float scr0 = sc_s[r0];
        const float scr1 = sc_s[r0 + 8];
#pragma unroll
        for (int nf = 0; nf < 8; ++nf) {
            accO[nf][0] *= scr0;
            accO[nf][1] *= scr0;
            accO[nf][2] *= scr1;
            accO[nf][3] *= scr1;
        }

        const uint32_t* Pw = (const uint32_t*)Ps + (warp_m * 16 + lr) * FP_STW + kc;
        const uint32_t vbase = v_su + buf * KV_TILE_BYTES +
                               (warp_n * 64) * 2;
#pragma unroll
        for (int ks = 0; ks < 2; ++ks) {
            uint32_t a[4];
            const uint32_t* ap = Pw + ks * 8;
            a[0] = ap[0];
            a[1] = ap[8 * FP_STW];
            a[2] = ap[4];
            a[3] = ap[8 * FP_STW + 4];
            const uint32_t rowaddr = vbase + ((ks * 16 + (lane & 15)) * FSTH) * 2;
#pragma unroll
            for (int nf = 0; nf < 8; ++nf) {
                uint32_t bfr[2];
                ldmatrix_x2_trans(bfr[0], bfr[1], rowaddr + nf * 16);
                mma_f16(accO[nf], a, bfr);
            }
        }
        __syncthreads();
    }

    // ---- normalize + write O fp16 ----
    const int row0 = warp_m * 16 + lr;
    const float inv0 = 1.0f / l_s[row0];
    const float inv1 = 1.0f / l_s[row0 + 8];
    __half* Og = O + head_base + (size_t)(qt * BQ) * DIM;
#pragma unroll
    for (int nf = 0; nf < 8; ++nf) {
        int col = warp_n * 64 + nf * 8 + kc * 2;
        *(__half2*)(Og + (size_t)row0 * DIM + col) =
            __floats2half2_rn(accO[nf][0] * inv0, accO[nf][1] * inv0);
        *(__half2*)(Og + (size_t)(row0 + 8) * DIM + col) =
            __floats2half2_rn(accO[nf][2] * inv1, accO[nf][3] * inv1);
    }
}

// ---------------------------------------------------------------------------
// Launch. Inputs: 0=x, 1=start_pos, 2=freqs_cos, 3=freqs_sin, 4=mask,
// 5=wq, 6=wk, 7=wv, 8=wo. Output: (B, S, DIM) fp32.
// ---------------------------------------------------------------------------
extern "C" void kernel_launch(void* const* d_in, const int* in_sizes, int n_in,
                              void* d_out, int out_size)
{
    const float* x  = (const float*)d_in[0];
    const float* fc = (const float*)d_in[2];
    const float* fs = (const float*)d_in[3];
    const float* wq = (const float*)d_in[5];
    const float* wk = (const float*)d_in[6];
    const float* wv = (const float*)d_in[7];
    const float* wo = (const float*)d_in[8];
    float* out = (float*)d_out;

    __half *qp, *kp, *vp, *ap, *xh, *wqh, *wkh, *wvh, *woh;
    cudaGetSymbolAddress((void**)&qp, g_q);
    cudaGetSymbolAddress((void**)&kp, g_k);
    cudaGetSymbolAddress((void**)&vp, g_v);
    cudaGetSymbolAddress((void**)&ap, g_att);
    cudaGetSymbolAddress((void**)&xh, g_xh);
    cudaGetSymbolAddress((void**)&wqh, g_wqh);
    cudaGetSymbolAddress((void**)&wkh, g_wkh);
    cudaGetSymbolAddress((void**)&wvh, g_wvh);
    cudaGetSymbolAddress((void**)&woh, g_woh);

    // pre-convert inputs to fp16
    const int n4x = (MROWS * DIM) / 4;
    const int n4w = (DIM * DIM) / 4;
    cvt_f16_kernel<<<(n4x + 255) / 256, 256>>>((const float4*)x, (uint2*)xh, n4x);
    cvt_f16_kernel<<<(n4w + 255) / 256, 256>>>((const float4*)wq, (uint2*)wqh, n4w);
    cvt_f16_kernel<<<(n4w + 255) / 256, 256>>>((const float4*)wk, (uint2*)wkh, n4w);
    cvt_f16_kernel<<<(n4w + 255) / 256, 256>>>((const float4*)wv, (uint2*)wvh, n4w);
    cvt_f16_kernel<<<(n4w + 255) / 256, 256>>>((const float4*)wo, (uint2*)woh, n4w);

    cudaFuncSetAttribute(gemm_f16_kernel,
                         cudaFuncAttributeMaxDynamicSharedMemorySize, GEMM_SMEM);

    // fused QKV projection + RoPE (+1/sqrt(hd) folded into q) -> fp16
    dim3 gq(DIM / GBN, MROWS / GBM, 3);
    gemm_f16_kernel<<<gq, 256, GEMM_SMEM>>>(xh, wqh, wkh, wvh,
                                            qp, kp, vp, fc, fs, 1);

    // flash attention (fp16 in/out)
    cudaFuncSetAttribute(flash_kernel,
                         cudaFuncAttributeMaxDynamicSharedMemorySize,
                         FLASH_SMEM_BYTES);
    dim3 fg(SEQLEN / BQ, BSZ * NH);
    flash_kernel<<<fg, 256, FLASH_SMEM_BYTES>>>(qp, kp, vp, ap);

    // output projection -> fp32
    dim3 go(DIM / GBN, MROWS / GBM, 1);
    gemm_f16_kernel<<<go, 256, GEMM_SMEM>>>(ap, woh, woh, woh,
                                            out, out, out, fc, fs, 0);
}